// round 1
// baseline (speedup 1.0000x reference)
#include <cuda_runtime.h>
#include <cuda_fp16.h>

#define BB 4
#define NN 4096
#define DD 64

// ---------------- scratch (device globals; no allocation allowed) ----------
__device__ __align__(16) __half g_A[(size_t)BB * NN * NN];   // 128 MiB, 0/1 fp16
__device__ float g_dinv[BB * NN];
__device__ __align__(16) __half g_t[BB * NN * DD];           // fp16 features (dinv_j * h@W)
__device__ __align__(16) float  g_h[BB * NN * DD];           // fp32 hidden state

// ---------------- threefry2x32 (Random123 / JAX) ---------------------------
__host__ __device__ constexpr unsigned rotl32(unsigned x, int r) {
  return (x << r) | (x >> (32 - r));
}

__host__ __device__ constexpr void tf2x32(unsigned k0, unsigned k1,
                                          unsigned& x0, unsigned& x1) {
  unsigned k2 = k0 ^ k1 ^ 0x1BD11BDAu;
  x0 += k0; x1 += k1;
  x0+=x1; x1=rotl32(x1,13); x1^=x0;
  x0+=x1; x1=rotl32(x1,15); x1^=x0;
  x0+=x1; x1=rotl32(x1,26); x1^=x0;
  x0+=x1; x1=rotl32(x1, 6); x1^=x0;
  x0+=k1; x1+=k2+1u;
  x0+=x1; x1=rotl32(x1,17); x1^=x0;
  x0+=x1; x1=rotl32(x1,29); x1^=x0;
  x0+=x1; x1=rotl32(x1,16); x1^=x0;
  x0+=x1; x1=rotl32(x1,24); x1^=x0;
  x0+=k2; x1+=k0+2u;
  x0+=x1; x1=rotl32(x1,13); x1^=x0;
  x0+=x1; x1=rotl32(x1,15); x1^=x0;
  x0+=x1; x1=rotl32(x1,26); x1^=x0;
  x0+=x1; x1=rotl32(x1, 6); x1^=x0;
  x0+=k0; x1+=k1+3u;
  x0+=x1; x1=rotl32(x1,17); x1^=x0;
  x0+=x1; x1=rotl32(x1,29); x1^=x0;
  x0+=x1; x1=rotl32(x1,16); x1^=x0;
  x0+=x1; x1=rotl32(x1,24); x1^=x0;
  x0+=k1; x1+=k2+4u;
  x0+=x1; x1=rotl32(x1,13); x1^=x0;
  x0+=x1; x1=rotl32(x1,15); x1^=x0;
  x0+=x1; x1=rotl32(x1,26); x1^=x0;
  x0+=x1; x1=rotl32(x1, 6); x1^=x0;
  x0+=k2; x1+=k0+5u;
}

struct KeyPair { unsigned a, b; };
// jax.random.key(42) -> key data (0,42); partitionable split is fold-like:
// new_key[i] = threefry2x32((0,42), (hi=0, lo=i))
__host__ __device__ constexpr KeyPair derive_key(unsigned ctr) {
  unsigned x0 = 0u, x1 = ctr;
  tf2x32(0u, 42u, x0, x1);
  return KeyPair{x0, x1};
}
constexpr KeyPair cK1 = derive_key(0u);
constexpr KeyPair cK2 = derive_key(1u);

// partitionable random_bits(32): bits = y0 ^ y1 of enc(key, (0, idx));
// uniform = bitcast((bits>>9)|0x3f800000) - 1 ; keep if u < 0.8 ; scale 1/0.8
__device__ __forceinline__ float drop_apply(float v, unsigned idx,
                                            unsigned ka, unsigned kb) {
  unsigned y0 = 0u, y1 = idx;
  tf2x32(ka, kb, y0, y1);
  unsigned bits = y0 ^ y1;
  float u = __uint_as_float((bits >> 9) | 0x3f800000u) - 1.0f;
  return (u < 0.8f) ? v * 1.25f : 0.0f;
}

// ---------------- kernel 1: degrees + A (fp16 0/1) -------------------------
__global__ __launch_bounds__(128) void prep_kernel(const int* __restrict__ adj) {
  int bi = blockIdx.x;                 // b*NN + i
  int i  = bi & (NN - 1);
  const int* row = adj + (size_t)bi * NN;
  __half* arow = g_A + (size_t)bi * NN;
  int tid = threadIdx.x;
  int cnt = 0;
#pragma unroll
  for (int s = 0; s < 8; s++) {
    int j4 = (tid + 128 * s) * 4;
    int4 v = *(const int4*)&row[j4];
    int a0 = (v.x != 0) || (j4 + 0 == i);
    int a1 = (v.y != 0) || (j4 + 1 == i);
    int a2 = (v.z != 0) || (j4 + 2 == i);
    int a3 = (v.w != 0) || (j4 + 3 == i);
    cnt += a0 + a1 + a2 + a3;
    unsigned lo = (a0 ? 0x3C00u : 0u) | (a1 ? 0x3C000000u : 0u);
    unsigned hi = (a2 ? 0x3C00u : 0u) | (a3 ? 0x3C000000u : 0u);
    *(uint2*)&arow[j4] = make_uint2(lo, hi);
  }
  // block reduce
  __shared__ int red[4];
  int wsum = __reduce_add_sync(0xffffffffu, cnt);
  if ((tid & 31) == 0) red[tid >> 5] = wsum;
  __syncthreads();
  if (tid == 0) {
    int total = red[0] + red[1] + red[2] + red[3];
    g_dinv[bi] = rsqrtf((float)total);
  }
}

// ---------------- kernel 2: t = fp16( dinv_j * (h @ W) ) -------------------
__global__ __launch_bounds__(256) void feat_kernel(const float* __restrict__ hin,
                                                   const float* __restrict__ W) {
  __shared__ float Ws[64][68];
  __shared__ float Xs[64][68];
  const float* src = hin ? hin : g_h;
  int tid = threadIdx.x;
  int r0 = blockIdx.x * 64;            // global row (flat over B*N)
#pragma unroll
  for (int s = 0; s < 4; s++) {
    int q = tid + 256 * s;
    int row = q >> 4, c = (q & 15) * 4;
    *(float4*)&Ws[row][c] = *(const float4*)&W[row * 64 + c];
    *(float4*)&Xs[row][c] = *(const float4*)&src[(size_t)(r0 + row) * 64 + c];
  }
  __syncthreads();
  int rl = tid >> 2;
  int d0 = (tid & 3) * 16;
  float acc[16];
#pragma unroll
  for (int i = 0; i < 16; i++) acc[i] = 0.0f;
#pragma unroll
  for (int k = 0; k < 64; k++) {
    float x = Xs[rl][k];
#pragma unroll
    for (int c = 0; c < 4; c++) {
      float4 w = *(float4*)&Ws[k][d0 + c * 4];
      acc[c * 4 + 0] += x * w.x;
      acc[c * 4 + 1] += x * w.y;
      acc[c * 4 + 2] += x * w.z;
      acc[c * 4 + 3] += x * w.w;
    }
  }
  int rg = r0 + rl;
  float sc = g_dinv[rg];
  __half hv[16];
#pragma unroll
  for (int i = 0; i < 16; i++) hv[i] = __float2half(sc * acc[i]);
  *(int4*)&g_t[(size_t)rg * 64 + d0] = *(int4*)&hv[0];
  *(int4*)&g_t[(size_t)rg * 64 + d0 + 8] = *(int4*)&hv[8];
}

// ---------------- mma helpers ----------------------------------------------
__device__ __forceinline__ void ldsm_x4(unsigned* r, const void* p) {
  unsigned addr = (unsigned)__cvta_generic_to_shared(p);
  asm volatile("ldmatrix.sync.aligned.m8n8.x4.shared.b16 {%0,%1,%2,%3}, [%4];"
               : "=r"(r[0]), "=r"(r[1]), "=r"(r[2]), "=r"(r[3]) : "r"(addr));
}
__device__ __forceinline__ void ldsm_x4_t(unsigned* r, const void* p) {
  unsigned addr = (unsigned)__cvta_generic_to_shared(p);
  asm volatile("ldmatrix.sync.aligned.m8n8.x4.trans.shared.b16 {%0,%1,%2,%3}, [%4];"
               : "=r"(r[0]), "=r"(r[1]), "=r"(r[2]), "=r"(r[3]) : "r"(addr));
}
__device__ __forceinline__ void mma16816(float* c, const unsigned* a,
                                         unsigned b0, unsigned b1) {
  asm volatile(
      "mma.sync.aligned.m16n8k16.row.col.f32.f16.f16.f32 "
      "{%0,%1,%2,%3}, {%4,%5,%6,%7}, {%8,%9}, {%0,%1,%2,%3};"
      : "+f"(c[0]), "+f"(c[1]), "+f"(c[2]), "+f"(c[3])
      : "r"(a[0]), "r"(a[1]), "r"(a[2]), "r"(a[3]), "r"(b0), "r"(b1));
}

// ---------------- kernel 3: out = dinv_i * (A @ t) + bias [; elu; dropout] -
__global__ __launch_bounds__(256) void agg_kernel(const float* __restrict__ bias,
                                                  float* __restrict__ outp,
                                                  unsigned ka, unsigned kb,
                                                  int do_drop) {
  __shared__ __half As[128][72];
  __shared__ __half Bs[64][72];
  float* out = outp ? outp : g_h;

  int b  = blockIdx.y;
  int i0 = blockIdx.x * 128;
  int tid = threadIdx.x;
  int wid = tid >> 5, lane = tid & 31;
  int warp_m = wid >> 1, warp_n = wid & 1;

  const __half* Arow = g_A + ((size_t)b * NN + i0) * NN;
  const __half* Bmat = g_t + (size_t)b * NN * DD;

  float acc[2][4][4];
#pragma unroll
  for (int mt = 0; mt < 2; mt++)
#pragma unroll
    for (int nt = 0; nt < 4; nt++)
#pragma unroll
      for (int c = 0; c < 4; c++) acc[mt][nt][c] = 0.0f;

  int lr = lane & 15;                 // ldmatrix row within 16
  int lc8 = ((lane >> 4) << 3);       // 0 or 8 column offset

  for (int kc = 0; kc < NN; kc += 64) {
    // fill A tile 128x64
#pragma unroll
    for (int s = 0; s < 4; s++) {
      int q = tid + 256 * s;
      int row = q >> 3, c8 = (q & 7) * 8;
      *(int4*)&As[row][c8] =
          *(const int4*)&Arow[(size_t)row * NN + kc + c8];
    }
    // fill B tile 64x64
#pragma unroll
    for (int s = 0; s < 2; s++) {
      int q = tid + 256 * s;
      int row = q >> 3, c8 = (q & 7) * 8;
      *(int4*)&Bs[row][c8] = *(const int4*)&Bmat[(size_t)(kc + row) * DD + c8];
    }
    __syncthreads();

#pragma unroll
    for (int ks = 0; ks < 4; ks++) {
      unsigned a[2][4], bf[2][4];
#pragma unroll
      for (int mt = 0; mt < 2; mt++)
        ldsm_x4(a[mt], &As[warp_m * 32 + mt * 16 + lr][ks * 16 + lc8]);
#pragma unroll
      for (int nh = 0; nh < 2; nh++)
        ldsm_x4_t(bf[nh], &Bs[ks * 16 + lr][warp_n * 32 + nh * 16 + lc8]);
#pragma unroll
      for (int mt = 0; mt < 2; mt++)
#pragma unroll
        for (int nt = 0; nt < 4; nt++)
          mma16816(acc[mt][nt], a[mt],
                   bf[nt >> 1][(nt & 1) * 2], bf[nt >> 1][(nt & 1) * 2 + 1]);
    }
    __syncthreads();
  }

  // epilogue
  int g = lane >> 2, tig = lane & 3;
#pragma unroll
  for (int mt = 0; mt < 2; mt++) {
#pragma unroll
    for (int hr = 0; hr < 2; hr++) {
      int i = i0 + warp_m * 32 + mt * 16 + g + hr * 8;
      float dv = g_dinv[b * NN + i];
#pragma unroll
      for (int nt = 0; nt < 4; nt++) {
#pragma unroll
        for (int c = 0; c < 2; c++) {
          int col = warp_n * 32 + nt * 8 + tig * 2 + c;
          float v = acc[mt][nt][hr * 2 + c] * dv + bias[col];
          unsigned idx = ((unsigned)(b * NN + i)) * 64u + (unsigned)col;
          if (do_drop) {
            v = (v > 0.0f) ? v : expm1f(v);     // ELU
            v = drop_apply(v, idx, ka, kb);     // JAX threefry dropout
          }
          out[idx] = v;
        }
      }
    }
  }
}

// ---------------- launch ----------------------------------------------------
extern "C" void kernel_launch(void* const* d_in, const int* in_sizes, int n_in,
                              void* d_out, int out_size) {
  const float* x  = (const float*)d_in[0];
  const int*   adj= (const int*)d_in[1];
  const float* W1 = (const float*)d_in[2];
  const float* b1 = (const float*)d_in[3];
  const float* W2 = (const float*)d_in[4];
  const float* b2 = (const float*)d_in[5];
  const float* W3 = (const float*)d_in[6];
  const float* b3 = (const float*)d_in[7];
  float* out = (float*)d_out;

  (void)in_sizes; (void)n_in; (void)out_size;

  prep_kernel<<<BB * NN, 128>>>(adj);

  dim3 agrid(NN / 128, BB);

  // layer 1
  feat_kernel<<<(BB * NN) / 64, 256>>>(x, W1);
  agg_kernel<<<agrid, 256>>>(b1, nullptr, cK1.a, cK1.b, 1);
  // layer 2
  feat_kernel<<<(BB * NN) / 64, 256>>>(nullptr, W2);
  agg_kernel<<<agrid, 256>>>(b2, nullptr, cK2.a, cK2.b, 1);
  // layer 3
  feat_kernel<<<(BB * NN) / 64, 256>>>(nullptr, W3);
  agg_kernel<<<agrid, 256>>>(b3, out, 0u, 0u, 0);
}

// round 2
// speedup vs baseline: 1.7599x; 1.7599x over previous
#include <cuda_runtime.h>
#include <cuda_fp16.h>

#define BB 4
#define NN 4096
#define DD 64

// ---------------- scratch (device globals; no allocation allowed) ----------
__device__ __align__(16) unsigned g_Ap[(size_t)BB * NN * (NN / 32)]; // 8 MiB bit-packed A
__device__ float g_dinv[BB * NN];
__device__ __align__(16) __half g_t[BB * NN * DD];   // fp16 features (dinv_j * h@W)
__device__ __align__(16) float  g_h[BB * NN * DD];   // fp32 hidden state

// ---------------- threefry2x32 (Random123 / JAX) ---------------------------
__host__ __device__ constexpr unsigned rotl32(unsigned x, int r) {
  return (x << r) | (x >> (32 - r));
}

__host__ __device__ constexpr void tf2x32(unsigned k0, unsigned k1,
                                          unsigned& x0, unsigned& x1) {
  unsigned k2 = k0 ^ k1 ^ 0x1BD11BDAu;
  x0 += k0; x1 += k1;
  x0+=x1; x1=rotl32(x1,13); x1^=x0;
  x0+=x1; x1=rotl32(x1,15); x1^=x0;
  x0+=x1; x1=rotl32(x1,26); x1^=x0;
  x0+=x1; x1=rotl32(x1, 6); x1^=x0;
  x0+=k1; x1+=k2+1u;
  x0+=x1; x1=rotl32(x1,17); x1^=x0;
  x0+=x1; x1=rotl32(x1,29); x1^=x0;
  x0+=x1; x1=rotl32(x1,16); x1^=x0;
  x0+=x1; x1=rotl32(x1,24); x1^=x0;
  x0+=k2; x1+=k0+2u;
  x0+=x1; x1=rotl32(x1,13); x1^=x0;
  x0+=x1; x1=rotl32(x1,15); x1^=x0;
  x0+=x1; x1=rotl32(x1,26); x1^=x0;
  x0+=x1; x1=rotl32(x1, 6); x1^=x0;
  x0+=k0; x1+=k1+3u;
  x0+=x1; x1=rotl32(x1,17); x1^=x0;
  x0+=x1; x1=rotl32(x1,29); x1^=x0;
  x0+=x1; x1=rotl32(x1,16); x1^=x0;
  x0+=x1; x1=rotl32(x1,24); x1^=x0;
  x0+=k1; x1+=k2+4u;
  x0+=x1; x1=rotl32(x1,13); x1^=x0;
  x0+=x1; x1=rotl32(x1,15); x1^=x0;
  x0+=x1; x1=rotl32(x1,26); x1^=x0;
  x0+=x1; x1=rotl32(x1, 6); x1^=x0;
  x0+=k2; x1+=k0+5u;
}

struct KeyPair { unsigned a, b; };
__host__ __device__ constexpr KeyPair derive_key(unsigned ctr) {
  unsigned x0 = 0u, x1 = ctr;
  tf2x32(0u, 42u, x0, x1);
  return KeyPair{x0, x1};
}
constexpr KeyPair cK1 = derive_key(0u);
constexpr KeyPair cK2 = derive_key(1u);

__device__ __forceinline__ float drop_apply(float v, unsigned idx,
                                            unsigned ka, unsigned kb) {
  unsigned y0 = 0u, y1 = idx;
  tf2x32(ka, kb, y0, y1);
  unsigned bits = y0 ^ y1;
  float u = __uint_as_float((bits >> 9) | 0x3f800000u) - 1.0f;
  return (u < 0.8f) ? v * 1.25f : 0.0f;
}

// ---------------- kernel 1: degrees + bit-packed A --------------------------
// one block per (b,i) row; thread t packs ints [t*32, t*32+32) into one word
__global__ __launch_bounds__(128) void prep_kernel(const int* __restrict__ adj) {
  int bi = blockIdx.x;                 // b*NN + i
  int i  = bi & (NN - 1);
  const int4* row4 = (const int4*)(adj + (size_t)bi * NN);
  int tid = threadIdx.x;
  unsigned word = 0u;
#pragma unroll
  for (int s = 0; s < 8; s++) {
    int4 v = row4[tid * 8 + s];
    unsigned m = (unsigned)(v.x != 0) | ((unsigned)(v.y != 0) << 1) |
                 ((unsigned)(v.z != 0) << 2) | ((unsigned)(v.w != 0) << 3);
    word |= m << (s * 4);
  }
  if ((i >> 5) == tid) word |= 1u << (i & 31);   // self loop
  g_Ap[(size_t)bi * 128 + tid] = word;

  int cnt = __popc(word);
  __shared__ int red[4];
  int wsum = __reduce_add_sync(0xffffffffu, cnt);
  if ((tid & 31) == 0) red[tid >> 5] = wsum;
  __syncthreads();
  if (tid == 0) {
    int total = red[0] + red[1] + red[2] + red[3];
    g_dinv[bi] = rsqrtf((float)total);
  }
}

// ---------------- kernel 2: t = fp16( dinv_j * (h @ W) ) -------------------
// 128 threads, 32 rows/CTA (4 threads per row, 16 cols each), X via L1 ldg
__global__ __launch_bounds__(128) void feat_kernel(const float* __restrict__ hin,
                                                   const float* __restrict__ W) {
  __shared__ float Ws[64][68];
  const float* src = hin ? hin : g_h;
  int tid = threadIdx.x;
  int r0 = blockIdx.x * 32;
#pragma unroll
  for (int s = 0; s < 8; s++) {
    int q = tid + 128 * s;
    int row = q >> 4, c = (q & 15) * 4;
    *(float4*)&Ws[row][c] = *(const float4*)&W[row * 64 + c];
  }
  __syncthreads();

  int rl = tid >> 2;
  int d0 = (tid & 3) * 16;
  int rg = r0 + rl;
  const float4* xr = (const float4*)&src[(size_t)rg * 64];

  float acc[16];
#pragma unroll
  for (int i = 0; i < 16; i++) acc[i] = 0.0f;

#pragma unroll
  for (int k4 = 0; k4 < 16; k4++) {
    float4 xv = xr[k4];
    float xs[4] = {xv.x, xv.y, xv.z, xv.w};
#pragma unroll
    for (int kk = 0; kk < 4; kk++) {
      int k = k4 * 4 + kk;
      float x = xs[kk];
#pragma unroll
      for (int c = 0; c < 4; c++) {
        float4 w = *(float4*)&Ws[k][d0 + c * 4];
        acc[c * 4 + 0] += x * w.x;
        acc[c * 4 + 1] += x * w.y;
        acc[c * 4 + 2] += x * w.z;
        acc[c * 4 + 3] += x * w.w;
      }
    }
  }
  float sc = g_dinv[rg];
  __half hv[16];
#pragma unroll
  for (int i = 0; i < 16; i++) hv[i] = __float2half(sc * acc[i]);
  *(int4*)&g_t[(size_t)rg * 64 + d0] = *(int4*)&hv[0];
  *(int4*)&g_t[(size_t)rg * 64 + d0 + 8] = *(int4*)&hv[8];
}

// ---------------- mma helpers ----------------------------------------------
__device__ __forceinline__ void ldsm_x4(unsigned* r, const void* p) {
  unsigned addr = (unsigned)__cvta_generic_to_shared(p);
  asm volatile("ldmatrix.sync.aligned.m8n8.x4.shared.b16 {%0,%1,%2,%3}, [%4];"
               : "=r"(r[0]), "=r"(r[1]), "=r"(r[2]), "=r"(r[3]) : "r"(addr));
}
__device__ __forceinline__ void ldsm_x4_t(unsigned* r, const void* p) {
  unsigned addr = (unsigned)__cvta_generic_to_shared(p);
  asm volatile("ldmatrix.sync.aligned.m8n8.x4.trans.shared.b16 {%0,%1,%2,%3}, [%4];"
               : "=r"(r[0]), "=r"(r[1]), "=r"(r[2]), "=r"(r[3]) : "r"(addr));
}
__device__ __forceinline__ void mma16816(float* c, const unsigned* a,
                                         unsigned b0, unsigned b1) {
  asm volatile(
      "mma.sync.aligned.m16n8k16.row.col.f32.f16.f16.f32 "
      "{%0,%1,%2,%3}, {%4,%5,%6,%7}, {%8,%9}, {%0,%1,%2,%3};"
      : "+f"(c[0]), "+f"(c[1]), "+f"(c[2]), "+f"(c[3])
      : "r"(a[0]), "r"(a[1]), "r"(a[2]), "r"(a[3]), "r"(b0), "r"(b1));
}

// expand 8 bits -> 8 fp16 (0/1) packed in uint4
__device__ __forceinline__ uint4 expand8(unsigned b) {
  uint4 v;
  v.x = ((b & 0x01u)        | ((b & 0x02u) << 15)) * 0x3C00u;
  v.y = (((b >> 2) & 1u)    | ((b & 0x08u) << 13)) * 0x3C00u;
  v.z = (((b >> 4) & 1u)    | ((b & 0x20u) << 11)) * 0x3C00u;
  v.w = (((b >> 6) & 1u)    | ((b & 0x80u) <<  9)) * 0x3C00u;
  return v;
}

// ---------------- kernel 3: out = dinv_i * (A @ t) + bias [; elu; dropout] -
// dynamic smem: As[128][136] fp16 then Bs[128][72] fp16
#define AS_STRIDE 136
#define BS_STRIDE 72
#define AS_BYTES (128 * AS_STRIDE * 2)
#define AGG_SMEM (AS_BYTES + 128 * BS_STRIDE * 2)

__global__ __launch_bounds__(256) void agg_kernel(const float* __restrict__ bias,
                                                  float* __restrict__ outp,
                                                  unsigned ka, unsigned kb,
                                                  int do_drop) {
  extern __shared__ __align__(16) char smem[];
  __half (*As)[AS_STRIDE] = (__half(*)[AS_STRIDE])smem;
  __half (*Bs)[BS_STRIDE] = (__half(*)[BS_STRIDE])(smem + AS_BYTES);
  float* out = outp ? outp : g_h;

  int b  = blockIdx.y;
  int i0 = blockIdx.x * 128;
  int tid = threadIdx.x;
  int wid = tid >> 5, lane = tid & 31;
  int warp_m = wid >> 1, warp_n = wid & 1;

  const unsigned* Ap = g_Ap + ((size_t)b * NN + i0) * 128;
  const __half* Bmat = g_t + (size_t)b * NN * DD;

  float acc[2][4][4];
#pragma unroll
  for (int mt = 0; mt < 2; mt++)
#pragma unroll
    for (int nt = 0; nt < 4; nt++)
#pragma unroll
      for (int c = 0; c < 4; c++) acc[mt][nt][c] = 0.0f;

  int lr = lane & 15;
  int lc8 = ((lane >> 4) << 3);

  int exp_row = tid >> 1;          // 0..127
  int exp_ws  = (tid & 1) * 2;     // word 0-1 or 2-3 of the chunk

  for (int kc = 0; kc < NN; kc += 128) {
    int kcw = kc >> 5;
    // expand packed A bits -> fp16 tile 128x128
#pragma unroll
    for (int t2 = 0; t2 < 2; t2++) {
      unsigned w = Ap[(size_t)exp_row * 128 + kcw + exp_ws + t2];
      int cbase = (exp_ws + t2) * 32;
#pragma unroll
      for (int g8 = 0; g8 < 4; g8++) {
        *(uint4*)&As[exp_row][cbase + g8 * 8] = expand8(w >> (g8 * 8));
      }
    }
    // fill B tile 128x64
#pragma unroll
    for (int s = 0; s < 4; s++) {
      int q = tid + 256 * s;
      int row = q >> 3, c8 = (q & 7) * 8;
      *(int4*)&Bs[row][c8] = *(const int4*)&Bmat[(size_t)(kc + row) * DD + c8];
    }
    __syncthreads();

#pragma unroll
    for (int ks = 0; ks < 8; ks++) {
      unsigned a[2][4], bf[2][4];
#pragma unroll
      for (int mt = 0; mt < 2; mt++)
        ldsm_x4(a[mt], &As[warp_m * 32 + mt * 16 + lr][ks * 16 + lc8]);
#pragma unroll
      for (int nh = 0; nh < 2; nh++)
        ldsm_x4_t(bf[nh], &Bs[ks * 16 + lr][warp_n * 32 + nh * 16 + lc8]);
#pragma unroll
      for (int mt = 0; mt < 2; mt++)
#pragma unroll
        for (int nt = 0; nt < 4; nt++)
          mma16816(acc[mt][nt], a[mt],
                   bf[nt >> 1][(nt & 1) * 2], bf[nt >> 1][(nt & 1) * 2 + 1]);
    }
    __syncthreads();
  }

  // epilogue
  int g = lane >> 2, tig = lane & 3;
#pragma unroll
  for (int mt = 0; mt < 2; mt++) {
#pragma unroll
    for (int hr = 0; hr < 2; hr++) {
      int i = i0 + warp_m * 32 + mt * 16 + g + hr * 8;
      float dv = g_dinv[b * NN + i];
#pragma unroll
      for (int nt = 0; nt < 4; nt++) {
#pragma unroll
        for (int c = 0; c < 2; c++) {
          int col = warp_n * 32 + nt * 8 + tig * 2 + c;
          float v = acc[mt][nt][hr * 2 + c] * dv + bias[col];
          unsigned idx = ((unsigned)(b * NN + i)) * 64u + (unsigned)col;
          if (do_drop) {
            v = (v > 0.0f) ? v : expm1f(v);     // ELU
            v = drop_apply(v, idx, ka, kb);     // JAX threefry dropout
          }
          out[idx] = v;
        }
      }
    }
  }
}

// ---------------- launch ----------------------------------------------------
extern "C" void kernel_launch(void* const* d_in, const int* in_sizes, int n_in,
                              void* d_out, int out_size) {
  const float* x  = (const float*)d_in[0];
  const int*   adj= (const int*)d_in[1];
  const float* W1 = (const float*)d_in[2];
  const float* b1 = (const float*)d_in[3];
  const float* W2 = (const float*)d_in[4];
  const float* b2 = (const float*)d_in[5];
  const float* W3 = (const float*)d_in[6];
  const float* b3 = (const float*)d_in[7];
  float* out = (float*)d_out;

  (void)in_sizes; (void)n_in; (void)out_size;

  cudaFuncSetAttribute(agg_kernel, cudaFuncAttributeMaxDynamicSharedMemorySize,
                       AGG_SMEM);

  prep_kernel<<<BB * NN, 128>>>(adj);

  dim3 agrid(NN / 128, BB);

  // layer 1
  feat_kernel<<<(BB * NN) / 32, 128>>>(x, W1);
  agg_kernel<<<agrid, 256, AGG_SMEM>>>(b1, nullptr, cK1.a, cK1.b, 1);
  // layer 2
  feat_kernel<<<(BB * NN) / 32, 128>>>(nullptr, W2);
  agg_kernel<<<agrid, 256, AGG_SMEM>>>(b2, nullptr, cK2.a, cK2.b, 1);
  // layer 3
  feat_kernel<<<(BB * NN) / 32, 128>>>(nullptr, W3);
  agg_kernel<<<agrid, 256, AGG_SMEM>>>(b3, out, 0u, 0u, 0);
}

// round 7
// speedup vs baseline: 1.9650x; 1.1165x over previous
#include <cuda_runtime.h>
#include <cuda_fp16.h>

#define BB 4
#define NN 4096
#define DD 64

// ---------------- scratch (device globals; no allocation allowed) ----------
__device__ __align__(16) unsigned g_Ap[(size_t)BB * NN * (NN / 32)]; // bit-packed A
__device__ float g_dinv[BB * NN];
// ping-pong fp16 feature buffers, row-major [b][j][d], pre-scaled by dinv_j
__device__ __align__(16) __half g_tb[2][(size_t)BB * NN * DD];

// ---------------- threefry2x32 (Random123 / JAX) ---------------------------
__host__ __device__ constexpr unsigned rotl32(unsigned x, int r) {
  return (x << r) | (x >> (32 - r));
}

__host__ __device__ constexpr void tf2x32(unsigned k0, unsigned k1,
                                          unsigned& x0, unsigned& x1) {
  unsigned k2 = k0 ^ k1 ^ 0x1BD11BDAu;
  x0 += k0; x1 += k1;
  x0+=x1; x1=rotl32(x1,13); x1^=x0;
  x0+=x1; x1=rotl32(x1,15); x1^=x0;
  x0+=x1; x1=rotl32(x1,26); x1^=x0;
  x0+=x1; x1=rotl32(x1, 6); x1^=x0;
  x0+=k1; x1+=k2+1u;
  x0+=x1; x1=rotl32(x1,17); x1^=x0;
  x0+=x1; x1=rotl32(x1,29); x1^=x0;
  x0+=x1; x1=rotl32(x1,16); x1^=x0;
  x0+=x1; x1=rotl32(x1,24); x1^=x0;
  x0+=k2; x1+=k0+2u;
  x0+=x1; x1=rotl32(x1,13); x1^=x0;
  x0+=x1; x1=rotl32(x1,15); x1^=x0;
  x0+=x1; x1=rotl32(x1,26); x1^=x0;
  x0+=x1; x1=rotl32(x1, 6); x1^=x0;
  x0+=k0; x1+=k1+3u;
  x0+=x1; x1=rotl32(x1,17); x1^=x0;
  x0+=x1; x1=rotl32(x1,29); x1^=x0;
  x0+=x1; x1=rotl32(x1,16); x1^=x0;
  x0+=x1; x1=rotl32(x1,24); x1^=x0;
  x0+=k1; x1+=k2+4u;
  x0+=x1; x1=rotl32(x1,13); x1^=x0;
  x0+=x1; x1=rotl32(x1,15); x1^=x0;
  x0+=x1; x1=rotl32(x1,26); x1^=x0;
  x0+=x1; x1=rotl32(x1, 6); x1^=x0;
  x0+=k2; x1+=k0+5u;
}

struct KeyPair { unsigned a, b; };
__host__ __device__ constexpr KeyPair derive_key(unsigned ctr) {
  unsigned x0 = 0u, x1 = ctr;
  tf2x32(0u, 42u, x0, x1);
  return KeyPair{x0, x1};
}
constexpr KeyPair cK1 = derive_key(0u);
constexpr KeyPair cK2 = derive_key(1u);

__device__ __forceinline__ float drop_apply(float v, unsigned idx,
                                            unsigned ka, unsigned kb) {
  unsigned y0 = 0u, y1 = idx;
  tf2x32(ka, kb, y0, y1);
  unsigned bits = y0 ^ y1;
  float u = __uint_as_float((bits >> 9) | 0x3f800000u) - 1.0f;
  return (u < 0.8f) ? v * 1.25f : 0.0f;
}

// ---------------- mma helpers (baseline sm_103-safe) ------------------------
__device__ __forceinline__ unsigned smem_u32(const void* p) {
  unsigned r;
  asm("{ .reg .u64 t; cvta.to.shared.u64 t, %1; cvt.u32.u64 %0, t; }"
      : "=r"(r) : "l"(p));
  return r;
}
__device__ __forceinline__ void ldsm_x4(unsigned* r, const void* p) {
  unsigned addr = smem_u32(p);
  asm volatile("ldmatrix.sync.aligned.m8n8.x4.shared.b16 {%0,%1,%2,%3}, [%4];"
               : "=r"(r[0]), "=r"(r[1]), "=r"(r[2]), "=r"(r[3]) : "r"(addr));
}
__device__ __forceinline__ void ldsm_x4_t(unsigned* r, const void* p) {
  unsigned addr = smem_u32(p);
  asm volatile("ldmatrix.sync.aligned.m8n8.x4.trans.shared.b16 {%0,%1,%2,%3}, [%4];"
               : "=r"(r[0]), "=r"(r[1]), "=r"(r[2]), "=r"(r[3]) : "r"(addr));
}
__device__ __forceinline__ void mma16816(float* c, const unsigned* a,
                                         unsigned b0, unsigned b1) {
  asm volatile(
      "mma.sync.aligned.m16n8k16.row.col.f32.f16.f16.f32 "
      "{%0,%1,%2,%3}, {%4,%5,%6,%7}, {%8,%9}, {%0,%1,%2,%3};"
      : "+f"(c[0]), "+f"(c[1]), "+f"(c[2]), "+f"(c[3])
      : "r"(a[0]), "r"(a[1]), "r"(a[2]), "r"(a[3]), "r"(b0), "r"(b1));
}

// expand 8 bits -> 8 fp16 (0/1) packed in uint4
__device__ __forceinline__ uint4 expand8(unsigned b) {
  uint4 v;
  v.x = ((b & 0x01u)     | ((b & 0x02u) << 15)) * 0x3C00u;
  v.y = (((b >> 2) & 1u) | ((b & 0x08u) << 13)) * 0x3C00u;
  v.z = (((b >> 4) & 1u) | ((b & 0x20u) << 11)) * 0x3C00u;
  v.w = (((b >> 6) & 1u) | ((b & 0x80u) <<  9)) * 0x3C00u;
  return v;
}

// ---------------- kernel 1: degrees + bit-packed A --------------------------
__global__ __launch_bounds__(128) void prep_kernel(const int* __restrict__ adj) {
  int bi = blockIdx.x;
  int i  = bi & (NN - 1);
  const int4* row4 = (const int4*)(adj + (size_t)bi * NN);
  int tid = threadIdx.x;
  unsigned word = 0u;
#pragma unroll
  for (int s = 0; s < 8; s++) {
    int4 v = row4[tid * 8 + s];
    unsigned m = (unsigned)(v.x != 0) | ((unsigned)(v.y != 0) << 1) |
                 ((unsigned)(v.z != 0) << 2) | ((unsigned)(v.w != 0) << 3);
    word |= m << (s * 4);
  }
  if ((i >> 5) == tid) word |= 1u << (i & 31);
  g_Ap[(size_t)bi * 128 + tid] = word;

  int cnt = __popc(word);
  __shared__ int red[4];
  int wsum = __reduce_add_sync(0xffffffffu, cnt);
  if ((tid & 31) == 0) red[tid >> 5] = wsum;
  __syncthreads();
  if (tid == 0) {
    int total = red[0] + red[1] + red[2] + red[3];
    g_dinv[bi] = rsqrtf((float)total);
  }
}

// ---------------- kernel 1b: t0[j][d] = fp16(dinv_j * x[j][d]) --------------
__global__ __launch_bounds__(256) void scalex_kernel(const float* __restrict__ x) {
  int idx = blockIdx.x * 256 + threadIdx.x;      // one per 8 elements
  size_t base = (size_t)idx * 8;
  int j = (int)(base >> 6);                       // flat row b*NN+j
  float dv = g_dinv[j];
  float4 v0 = *(const float4*)&x[base];
  float4 v1 = *(const float4*)&x[base + 4];
  __half h[8];
  h[0] = __float2half(v0.x * dv); h[1] = __float2half(v0.y * dv);
  h[2] = __float2half(v0.z * dv); h[3] = __float2half(v0.w * dv);
  h[4] = __float2half(v1.x * dv); h[5] = __float2half(v1.y * dv);
  h[6] = __float2half(v1.z * dv); h[7] = __float2half(v1.w * dv);
  *(uint4*)&g_tb[0][base] = *(uint4*)h;
}

// ---------------- kernel 2: fused  out = dinv_i*(A@t)@W + b [; elu; drop] ---
#define AS_STRIDE 136
#define BS_STRIDE 72
#define OFF_B0 0
#define OFF_B1 18432
#define OFF_A0 36864
#define OFF_A1 71680
#define OFF_WHI 106496
#define OFF_WLO 115712
#define AGG_DYN 124928

__global__ __launch_bounds__(256) void agg_kernel(
    const float* __restrict__ Wm, const float* __restrict__ bias,
    float* __restrict__ outp, int tin_sel,
    unsigned ka, unsigned kb, int do_drop) {
  extern __shared__ __align__(16) char smem[];
  __half* Whi = (__half*)(smem + OFF_WHI);
  __half* Wlo = (__half*)(smem + OFF_WLO);

  int tid = threadIdx.x, wid = tid >> 5, lane = tid & 31;
  int warp_m = wid >> 1, warp_n = wid & 1;
  int b = blockIdx.y, i0 = blockIdx.x * 128;

  // W hi/lo split
#pragma unroll
  for (int s = 0; s < 16; s++) {
    int idx = tid + 256 * s;
    int r = idx >> 6, c = idx & 63;
    float w = Wm[idx];
    __half hh = __float2half(w);
    Whi[r * BS_STRIDE + c] = hh;
    Wlo[r * BS_STRIDE + c] = __float2half(w - __half2float(hh));
  }

  const unsigned* Ap = g_Ap + ((size_t)b * NN + i0) * 128;
  const __half* tin = g_tb[tin_sel] + (size_t)b * NN * DD;
  __half* tout = g_tb[tin_sel ^ 1] + (size_t)b * NN * DD;

  // fill thread mapping
  int arow = tid & 127;            // A row handled by this thread
  int aw2  = (tid >> 7) * 2;       // first of 2 words within the chunk

  float acc[2][4][4];
#pragma unroll
  for (int mt = 0; mt < 2; mt++)
#pragma unroll
    for (int nt = 0; nt < 4; nt++)
#pragma unroll
      for (int q = 0; q < 4; q++) acc[mt][nt][q] = 0.0f;

  int lr = lane & 15, lc8 = (lane >> 4) << 3;

  // prologue: fill buffer 0 (chunk 0)
  {
    __half (*As)[AS_STRIDE] = (__half(*)[AS_STRIDE])(smem + OFF_A0);
    __half (*Bs)[BS_STRIDE] = (__half(*)[BS_STRIDE])(smem + OFF_B0);
    uint2 wp = *(const uint2*)&Ap[(size_t)arow * 128 + aw2];
#pragma unroll
    for (int t2 = 0; t2 < 2; t2++) {
      unsigned bits = t2 ? wp.y : wp.x;
      int wloc = aw2 + t2;
#pragma unroll
      for (int g8 = 0; g8 < 4; g8++)
        *(uint4*)&As[arow][wloc * 32 + g8 * 8] = expand8(bits >> (g8 * 8));
    }
#pragma unroll
    for (int s = 0; s < 4; s++) {
      int q = tid + 256 * s;
      int row = q >> 3, seg = (q & 7) * 8;
      *(uint4*)&Bs[row][seg] = *(const uint4*)&tin[(size_t)row * DD + seg];
    }
  }
  __syncthreads();

  for (int c = 0; c < 32; c++) {
    int cur = c & 1;
    __half (*As)[AS_STRIDE] =
        (__half(*)[AS_STRIDE])(smem + (cur ? OFF_A1 : OFF_A0));
    __half (*Bs)[BS_STRIDE] =
        (__half(*)[BS_STRIDE])(smem + (cur ? OFF_B1 : OFF_B0));
    // fill next buffer (overlaps with MMA below)
    if (c < 31) {
      int kn = (c + 1) * 128;
      __half (*An)[AS_STRIDE] =
          (__half(*)[AS_STRIDE])(smem + (cur ? OFF_A0 : OFF_A1));
      __half (*Bn)[BS_STRIDE] =
          (__half(*)[BS_STRIDE])(smem + (cur ? OFF_B0 : OFF_B1));
      uint2 wp = *(const uint2*)&Ap[(size_t)arow * 128 + (kn >> 5) + aw2];
#pragma unroll
      for (int t2 = 0; t2 < 2; t2++) {
        unsigned bits = t2 ? wp.y : wp.x;
        int wloc = aw2 + t2;
#pragma unroll
        for (int g8 = 0; g8 < 4; g8++)
          *(uint4*)&An[arow][wloc * 32 + g8 * 8] = expand8(bits >> (g8 * 8));
      }
#pragma unroll
      for (int s = 0; s < 4; s++) {
        int q = tid + 256 * s;
        int row = q >> 3, seg = (q & 7) * 8;
        *(uint4*)&Bn[row][seg] = *(const uint4*)&tin[(size_t)(kn + row) * DD + seg];
      }
    }
    // MMA on current buffer
#pragma unroll
    for (int ks = 0; ks < 8; ks++) {
      unsigned a[2][4], bf[2][4];
#pragma unroll
      for (int mt = 0; mt < 2; mt++)
        ldsm_x4(a[mt], &As[warp_m * 32 + mt * 16 + lr][ks * 16 + lc8]);
#pragma unroll
      for (int nh = 0; nh < 2; nh++)
        ldsm_x4_t(bf[nh], &Bs[ks * 16 + lr][warp_n * 32 + nh * 16 + lc8]);
#pragma unroll
      for (int mt = 0; mt < 2; mt++)
#pragma unroll
        for (int nt = 0; nt < 4; nt++)
          mma16816(acc[mt][nt], a[mt],
                   bf[nt >> 1][(nt & 1) * 2], bf[nt >> 1][(nt & 1) * 2 + 1]);
    }
    __syncthreads();
  }

  // stage Cs = fp16(dinv_i * C) into smem (reuse B0 region)
  __half* Cs = (__half*)(smem + OFF_B0);
  int g = lane >> 2, tig = lane & 3;
#pragma unroll
  for (int mt = 0; mt < 2; mt++) {
#pragma unroll
    for (int hr = 0; hr < 2; hr++) {
      int il = warp_m * 32 + mt * 16 + g + hr * 8;
      float dv = g_dinv[b * NN + i0 + il];
#pragma unroll
      for (int nt = 0; nt < 4; nt++) {
        int col = warp_n * 32 + nt * 8 + tig * 2;
        __half2 hv = __floats2half2_rn(acc[mt][nt][hr * 2] * dv,
                                       acc[mt][nt][hr * 2 + 1] * dv);
        *(__half2*)&Cs[il * BS_STRIDE + col] = hv;
      }
    }
  }
  __syncthreads();

  // W-multiply: D = Cs @ (Whi + Wlo); each warp: rows wid*16..+15, all 64 cols
  float acc2[8][4];
#pragma unroll
  for (int nt = 0; nt < 8; nt++)
#pragma unroll
    for (int q = 0; q < 4; q++) acc2[nt][q] = 0.0f;

  int rw = wid * 16;
#pragma unroll
  for (int ks = 0; ks < 4; ks++) {
    unsigned a2[4], bh[4][4], bl[4][4];
    ldsm_x4(a2, &Cs[(rw + lr) * BS_STRIDE + ks * 16 + lc8]);
#pragma unroll
    for (int nh = 0; nh < 4; nh++) {
      ldsm_x4_t(bh[nh], &Whi[(ks * 16 + lr) * BS_STRIDE + nh * 16 + lc8]);
      ldsm_x4_t(bl[nh], &Wlo[(ks * 16 + lr) * BS_STRIDE + nh * 16 + lc8]);
    }
#pragma unroll
    for (int nt = 0; nt < 8; nt++) {
      mma16816(acc2[nt], a2, bh[nt >> 1][(nt & 1) * 2],
               bh[nt >> 1][(nt & 1) * 2 + 1]);
      mma16816(acc2[nt], a2, bl[nt >> 1][(nt & 1) * 2],
               bl[nt >> 1][(nt & 1) * 2 + 1]);
    }
  }

  // final epilogue
#pragma unroll
  for (int hr = 0; hr < 2; hr++) {
    int i = i0 + rw + g + hr * 8;
    float dv = g_dinv[b * NN + i];
#pragma unroll
    for (int nt = 0; nt < 8; nt++) {
#pragma unroll
      for (int c2 = 0; c2 < 2; c2++) {
        int col = nt * 8 + tig * 2 + c2;
        float v = acc2[nt][hr * 2 + c2] + __ldg(&bias[col]);
        unsigned idx = ((unsigned)(b * NN + i)) * 64u + (unsigned)col;
        if (do_drop) {
          v = (v > 0.0f) ? v : expm1f(v);      // ELU
          v = drop_apply(v, idx, ka, kb);      // JAX threefry dropout
          tout[(size_t)(i)*DD + col] = __float2half(v * dv);
        } else {
          outp[idx] = v;
        }
      }
    }
  }
}

// ---------------- launch ----------------------------------------------------
extern "C" void kernel_launch(void* const* d_in, const int* in_sizes, int n_in,
                              void* d_out, int out_size) {
  const float* x  = (const float*)d_in[0];
  const int*   adj= (const int*)d_in[1];
  const float* W1 = (const float*)d_in[2];
  const float* b1 = (const float*)d_in[3];
  const float* W2 = (const float*)d_in[4];
  const float* b2 = (const float*)d_in[5];
  const float* W3 = (const float*)d_in[6];
  const float* b3 = (const float*)d_in[7];
  float* out = (float*)d_out;

  (void)in_sizes; (void)n_in; (void)out_size;

  cudaFuncSetAttribute(agg_kernel, cudaFuncAttributeMaxDynamicSharedMemorySize,
                       AGG_DYN);

  prep_kernel<<<BB * NN, 128>>>(adj);
  scalex_kernel<<<(BB * NN * DD) / 8 / 256, 256>>>(x);

  dim3 agrid(NN / 128, BB);
  agg_kernel<<<agrid, 256, AGG_DYN>>>(W1, b1, nullptr, 0, cK1.a, cK1.b, 1);
  agg_kernel<<<agrid, 256, AGG_DYN>>>(W2, b2, nullptr, 1, cK2.a, cK2.b, 1);
  agg_kernel<<<agrid, 256, AGG_DYN>>>(W3, b3, out, 0, 0u, 0u, 0);
}

// round 8
// speedup vs baseline: 2.0161x; 1.0260x over previous
#include <cuda_runtime.h>
#include <cuda_fp16.h>

#define BB 4
#define NN 4096
#define DD 64

// ---------------- scratch (device globals; no allocation allowed) ----------
__device__ __align__(16) unsigned g_Ap[(size_t)BB * NN * (NN / 32)]; // bit-packed A
__device__ float g_dinv[BB * NN];
// ping-pong fp16 feature buffers, row-major [b][j][d], pre-scaled by dinv_j
__device__ __align__(16) __half g_tb[2][(size_t)BB * NN * DD];

// ---------------- threefry2x32 (Random123 / JAX) ---------------------------
__host__ __device__ constexpr unsigned rotl32(unsigned x, int r) {
  return (x << r) | (x >> (32 - r));
}

__host__ __device__ constexpr void tf2x32(unsigned k0, unsigned k1,
                                          unsigned& x0, unsigned& x1) {
  unsigned k2 = k0 ^ k1 ^ 0x1BD11BDAu;
  x0 += k0; x1 += k1;
  x0+=x1; x1=rotl32(x1,13); x1^=x0;
  x0+=x1; x1=rotl32(x1,15); x1^=x0;
  x0+=x1; x1=rotl32(x1,26); x1^=x0;
  x0+=x1; x1=rotl32(x1, 6); x1^=x0;
  x0+=k1; x1+=k2+1u;
  x0+=x1; x1=rotl32(x1,17); x1^=x0;
  x0+=x1; x1=rotl32(x1,29); x1^=x0;
  x0+=x1; x1=rotl32(x1,16); x1^=x0;
  x0+=x1; x1=rotl32(x1,24); x1^=x0;
  x0+=k2; x1+=k0+2u;
  x0+=x1; x1=rotl32(x1,13); x1^=x0;
  x0+=x1; x1=rotl32(x1,15); x1^=x0;
  x0+=x1; x1=rotl32(x1,26); x1^=x0;
  x0+=x1; x1=rotl32(x1, 6); x1^=x0;
  x0+=k0; x1+=k1+3u;
  x0+=x1; x1=rotl32(x1,17); x1^=x0;
  x0+=x1; x1=rotl32(x1,29); x1^=x0;
  x0+=x1; x1=rotl32(x1,16); x1^=x0;
  x0+=x1; x1=rotl32(x1,24); x1^=x0;
  x0+=k1; x1+=k2+4u;
  x0+=x1; x1=rotl32(x1,13); x1^=x0;
  x0+=x1; x1=rotl32(x1,15); x1^=x0;
  x0+=x1; x1=rotl32(x1,26); x1^=x0;
  x0+=x1; x1=rotl32(x1, 6); x1^=x0;
  x0+=k2; x1+=k0+5u;
}

struct KeyPair { unsigned a, b; };
__host__ __device__ constexpr KeyPair derive_key(unsigned ctr) {
  unsigned x0 = 0u, x1 = ctr;
  tf2x32(0u, 42u, x0, x1);
  return KeyPair{x0, x1};
}
constexpr KeyPair cK1 = derive_key(0u);
constexpr KeyPair cK2 = derive_key(1u);

__device__ __forceinline__ float drop_apply(float v, unsigned idx,
                                            unsigned ka, unsigned kb) {
  unsigned y0 = 0u, y1 = idx;
  tf2x32(ka, kb, y0, y1);
  unsigned bits = y0 ^ y1;
  float u = __uint_as_float((bits >> 9) | 0x3f800000u) - 1.0f;
  return (u < 0.8f) ? v * 1.25f : 0.0f;
}

// ---------------- mma helpers (baseline sm_103-safe) ------------------------
__device__ __forceinline__ unsigned smem_u32(const void* p) {
  unsigned r;
  asm("{ .reg .u64 t; cvta.to.shared.u64 t, %1; cvt.u32.u64 %0, t; }"
      : "=r"(r) : "l"(p));
  return r;
}
__device__ __forceinline__ void ldsm_x4(unsigned* r, const void* p) {
  unsigned addr = smem_u32(p);
  asm volatile("ldmatrix.sync.aligned.m8n8.x4.shared.b16 {%0,%1,%2,%3}, [%4];"
               : "=r"(r[0]), "=r"(r[1]), "=r"(r[2]), "=r"(r[3]) : "r"(addr));
}
__device__ __forceinline__ void ldsm_x4_t(unsigned* r, const void* p) {
  unsigned addr = smem_u32(p);
  asm volatile("ldmatrix.sync.aligned.m8n8.x4.trans.shared.b16 {%0,%1,%2,%3}, [%4];"
               : "=r"(r[0]), "=r"(r[1]), "=r"(r[2]), "=r"(r[3]) : "r"(addr));
}
__device__ __forceinline__ void mma16816(float* c, const unsigned* a,
                                         unsigned b0, unsigned b1) {
  asm volatile(
      "mma.sync.aligned.m16n8k16.row.col.f32.f16.f16.f32 "
      "{%0,%1,%2,%3}, {%4,%5,%6,%7}, {%8,%9}, {%0,%1,%2,%3};"
      : "+f"(c[0]), "+f"(c[1]), "+f"(c[2]), "+f"(c[3])
      : "r"(a[0]), "r"(a[1]), "r"(a[2]), "r"(a[3]), "r"(b0), "r"(b1));
}

// expand 8 bits -> 8 fp16 (0/1) packed in uint4
__device__ __forceinline__ uint4 expand8(unsigned b) {
  uint4 v;
  v.x = ((b & 0x01u)     | ((b & 0x02u) << 15)) * 0x3C00u;
  v.y = (((b >> 2) & 1u) | ((b & 0x08u) << 13)) * 0x3C00u;
  v.z = (((b >> 4) & 1u) | ((b & 0x20u) << 11)) * 0x3C00u;
  v.w = (((b >> 6) & 1u) | ((b & 0x80u) <<  9)) * 0x3C00u;
  return v;
}

// ---------------- kernel 1: degrees + bit-packed A --------------------------
__global__ __launch_bounds__(128) void prep_kernel(const int* __restrict__ adj) {
  int bi = blockIdx.x;
  int i  = bi & (NN - 1);
  const int4* row4 = (const int4*)(adj + (size_t)bi * NN);
  int tid = threadIdx.x;
  unsigned word = 0u;
#pragma unroll
  for (int s = 0; s < 8; s++) {
    int4 v = row4[tid * 8 + s];
    unsigned m = (unsigned)(v.x != 0) | ((unsigned)(v.y != 0) << 1) |
                 ((unsigned)(v.z != 0) << 2) | ((unsigned)(v.w != 0) << 3);
    word |= m << (s * 4);
  }
  if ((i >> 5) == tid) word |= 1u << (i & 31);
  g_Ap[(size_t)bi * 128 + tid] = word;

  int cnt = __popc(word);
  __shared__ int red[4];
  int wsum = __reduce_add_sync(0xffffffffu, cnt);
  if ((tid & 31) == 0) red[tid >> 5] = wsum;
  __syncthreads();
  if (tid == 0) {
    int total = red[0] + red[1] + red[2] + red[3];
    g_dinv[bi] = rsqrtf((float)total);
  }
}

// ---------------- kernel 1b: t0[j][d] = fp16(dinv_j * x[j][d]) --------------
__global__ __launch_bounds__(256) void scalex_kernel(const float* __restrict__ x) {
  int idx = blockIdx.x * 256 + threadIdx.x;      // one per 8 elements
  size_t base = (size_t)idx * 8;
  int j = (int)(base >> 6);                       // flat row b*NN+j
  float dv = g_dinv[j];
  float4 v0 = *(const float4*)&x[base];
  float4 v1 = *(const float4*)&x[base + 4];
  __half h[8];
  h[0] = __float2half(v0.x * dv); h[1] = __float2half(v0.y * dv);
  h[2] = __float2half(v0.z * dv); h[3] = __float2half(v0.w * dv);
  h[4] = __float2half(v1.x * dv); h[5] = __float2half(v1.y * dv);
  h[6] = __float2half(v1.z * dv); h[7] = __float2half(v1.w * dv);
  *(uint4*)&g_tb[0][base] = *(uint4*)h;
}

// ---------------- kernel 2: fused  out = dinv_i*(A@t)@W + b [; elu; drop] ---
// M-tile = 64, K-chunk = 128, 256 threads, 2 CTAs/SM.
#define AS_STRIDE 136
#define BS_STRIDE 72
#define OFF_B0 0
#define OFF_B1 18432
#define OFF_A0 36864
#define OFF_A1 54272
#define OFF_WHI 71680
#define OFF_WLO 80896
#define AGG_DYN 90112

__global__ __launch_bounds__(256, 2) void agg_kernel(
    const float* __restrict__ Wm, const float* __restrict__ bias,
    float* __restrict__ outp, int tin_sel,
    unsigned ka, unsigned kb, int do_drop) {
  extern __shared__ __align__(16) char smem[];
  __half* Whi = (__half*)(smem + OFF_WHI);
  __half* Wlo = (__half*)(smem + OFF_WLO);

  int tid = threadIdx.x, wid = tid >> 5, lane = tid & 31;
  int warp_m = wid >> 2, warp_n = wid & 3;   // 2 x 4 warp grid
  int b = blockIdx.y, i0 = blockIdx.x * 64;

  // W hi/lo split
#pragma unroll
  for (int s = 0; s < 16; s++) {
    int idx = tid + 256 * s;
    int r = idx >> 6, c = idx & 63;
    float w = Wm[idx];
    __half hh = __float2half(w);
    Whi[r * BS_STRIDE + c] = hh;
    Wlo[r * BS_STRIDE + c] = __float2half(w - __half2float(hh));
  }

  const unsigned* Ap = g_Ap + ((size_t)b * NN + i0) * 128;
  const __half* tin = g_tb[tin_sel] + (size_t)b * NN * DD;
  __half* tout = g_tb[tin_sel ^ 1] + (size_t)b * NN * DD;

  // fill mapping: A -> 64 rows x 4 words, one word per thread
  int arow = tid & 63;
  int awo  = tid >> 6;             // word 0..3 within chunk

  float acc[2][2][4];
#pragma unroll
  for (int mt = 0; mt < 2; mt++)
#pragma unroll
    for (int nt = 0; nt < 2; nt++)
#pragma unroll
      for (int q = 0; q < 4; q++) acc[mt][nt][q] = 0.0f;

  int lr = lane & 15, lc8 = (lane >> 4) << 3;

  // staged registers
  unsigned aw;
  uint4 bv[4];

  // preload + store chunk 0 into buffer 0
  aw = Ap[(size_t)arow * 128 + awo];
#pragma unroll
  for (int s = 0; s < 4; s++) {
    int q = tid + 256 * s;
    bv[s] = *(const uint4*)&tin[(size_t)(q >> 3) * DD + (q & 7) * 8];
  }
  {
    __half (*As)[AS_STRIDE] = (__half(*)[AS_STRIDE])(smem + OFF_A0);
    __half (*Bs)[BS_STRIDE] = (__half(*)[BS_STRIDE])(smem + OFF_B0);
#pragma unroll
    for (int g8 = 0; g8 < 4; g8++)
      *(uint4*)&As[arow][awo * 32 + g8 * 8] = expand8(aw >> (g8 * 8));
#pragma unroll
    for (int s = 0; s < 4; s++) {
      int q = tid + 256 * s;
      *(uint4*)&Bs[q >> 3][(q & 7) * 8] = bv[s];
    }
  }
  __syncthreads();

  for (int c = 0; c < 32; c++) {
    int cur = c & 1;
    __half (*As)[AS_STRIDE] =
        (__half(*)[AS_STRIDE])(smem + (cur ? OFF_A1 : OFF_A0));
    __half (*Bs)[BS_STRIDE] =
        (__half(*)[BS_STRIDE])(smem + (cur ? OFF_B1 : OFF_B0));
    // issue global loads for chunk c+1 (latency hidden behind MMAs)
    if (c < 31) {
      int kn = (c + 1) * 128;
      aw = Ap[(size_t)arow * 128 + (kn >> 5) + awo];
#pragma unroll
      for (int s = 0; s < 4; s++) {
        int q = tid + 256 * s;
        bv[s] = *(const uint4*)&tin[(size_t)(kn + (q >> 3)) * DD + (q & 7) * 8];
      }
    }
    // MMA on current buffer
#pragma unroll
    for (int ks = 0; ks < 8; ks++) {
      unsigned a[2][4], bf[4];
#pragma unroll
      for (int mt = 0; mt < 2; mt++)
        ldsm_x4(a[mt], &As[warp_m * 32 + mt * 16 + lr][ks * 16 + lc8]);
      ldsm_x4_t(bf, &Bs[ks * 16 + lr][warp_n * 16 + lc8]);
#pragma unroll
      for (int mt = 0; mt < 2; mt++)
#pragma unroll
        for (int nt = 0; nt < 2; nt++)
          mma16816(acc[mt][nt], a[mt], bf[nt * 2], bf[nt * 2 + 1]);
    }
    // store staged chunk c+1
    if (c < 31) {
      __half (*An)[AS_STRIDE] =
          (__half(*)[AS_STRIDE])(smem + (cur ? OFF_A0 : OFF_A1));
      __half (*Bn)[BS_STRIDE] =
          (__half(*)[BS_STRIDE])(smem + (cur ? OFF_B0 : OFF_B1));
#pragma unroll
      for (int g8 = 0; g8 < 4; g8++)
        *(uint4*)&An[arow][awo * 32 + g8 * 8] = expand8(aw >> (g8 * 8));
#pragma unroll
      for (int s = 0; s < 4; s++) {
        int q = tid + 256 * s;
        *(uint4*)&Bn[q >> 3][(q & 7) * 8] = bv[s];
      }
    }
    __syncthreads();
  }

  // stage Cs = fp16(dinv_i * C) into smem (reuse B0 region; 64 x 72)
  __half* Cs = (__half*)(smem + OFF_B0);
  int g = lane >> 2, tig = lane & 3;
#pragma unroll
  for (int mt = 0; mt < 2; mt++) {
#pragma unroll
    for (int hr = 0; hr < 2; hr++) {
      int il = warp_m * 32 + mt * 16 + g + hr * 8;
      float dv = g_dinv[b * NN + i0 + il];
#pragma unroll
      for (int nt = 0; nt < 2; nt++) {
        int col = warp_n * 16 + nt * 8 + tig * 2;
        __half2 hv = __floats2half2_rn(acc[mt][nt][hr * 2] * dv,
                                       acc[mt][nt][hr * 2 + 1] * dv);
        *(__half2*)&Cs[il * BS_STRIDE + col] = hv;
      }
    }
  }
  __syncthreads();

  // W-multiply: D = Cs @ (Whi + Wlo); warp tile M32 x N16, K=64
  float acc2[2][2][4];
#pragma unroll
  for (int mt = 0; mt < 2; mt++)
#pragma unroll
    for (int nt = 0; nt < 2; nt++)
#pragma unroll
      for (int q = 0; q < 4; q++) acc2[mt][nt][q] = 0.0f;

#pragma unroll
  for (int ks = 0; ks < 4; ks++) {
    unsigned a2[2][4], bh[4], bl[4];
#pragma unroll
    for (int mt = 0; mt < 2; mt++)
      ldsm_x4(a2[mt], &Cs[(warp_m * 32 + mt * 16 + lr) * BS_STRIDE + ks * 16 + lc8]);
    ldsm_x4_t(bh, &Whi[(ks * 16 + lr) * BS_STRIDE + warp_n * 16 + lc8]);
    ldsm_x4_t(bl, &Wlo[(ks * 16 + lr) * BS_STRIDE + warp_n * 16 + lc8]);
#pragma unroll
    for (int mt = 0; mt < 2; mt++)
#pragma unroll
      for (int nt = 0; nt < 2; nt++) {
        mma16816(acc2[mt][nt], a2[mt], bh[nt * 2], bh[nt * 2 + 1]);
        mma16816(acc2[mt][nt], a2[mt], bl[nt * 2], bl[nt * 2 + 1]);
      }
  }

  // final epilogue
#pragma unroll
  for (int mt = 0; mt < 2; mt++) {
#pragma unroll
    for (int hr = 0; hr < 2; hr++) {
      int i = i0 + warp_m * 32 + mt * 16 + g + hr * 8;
      float dv = g_dinv[b * NN + i];
#pragma unroll
      for (int nt = 0; nt < 2; nt++) {
#pragma unroll
        for (int c2 = 0; c2 < 2; c2++) {
          int col = warp_n * 16 + nt * 8 + tig * 2 + c2;
          float v = acc2[mt][nt][hr * 2 + c2] + __ldg(&bias[col]);
          unsigned idx = ((unsigned)(b * NN + i)) * 64u + (unsigned)col;
          if (do_drop) {
            v = (v > 0.0f) ? v : expm1f(v);      // ELU
            v = drop_apply(v, idx, ka, kb);      // JAX threefry dropout
            tout[(size_t)i * DD + col] = __float2half(v * dv);
          } else {
            outp[idx] = v;
          }
        }
      }
    }
  }
}

// ---------------- launch ----------------------------------------------------
extern "C" void kernel_launch(void* const* d_in, const int* in_sizes, int n_in,
                              void* d_out, int out_size) {
  const float* x  = (const float*)d_in[0];
  const int*   adj= (const int*)d_in[1];
  const float* W1 = (const float*)d_in[2];
  const float* b1 = (const float*)d_in[3];
  const float* W2 = (const float*)d_in[4];
  const float* b2 = (const float*)d_in[5];
  const float* W3 = (const float*)d_in[6];
  const float* b3 = (const float*)d_in[7];
  float* out = (float*)d_out;

  (void)in_sizes; (void)n_in; (void)out_size;

  cudaFuncSetAttribute(agg_kernel, cudaFuncAttributeMaxDynamicSharedMemorySize,
                       AGG_DYN);

  prep_kernel<<<BB * NN, 128>>>(adj);
  scalex_kernel<<<(BB * NN * DD) / 8 / 256, 256>>>(x);

  dim3 agrid(NN / 64, BB);
  agg_kernel<<<agrid, 256, AGG_DYN>>>(W1, b1, nullptr, 0, cK1.a, cK1.b, 1);
  agg_kernel<<<agrid, 256, AGG_DYN>>>(W2, b2, nullptr, 1, cK2.a, cK2.b, 1);
  agg_kernel<<<agrid, 256, AGG_DYN>>>(W3, b3, out, 0, 0u, 0u, 0);
}

// round 9
// speedup vs baseline: 2.2123x; 1.0973x over previous
#include <cuda_runtime.h>
#include <cuda_fp16.h>

#define BB 4
#define NN 4096
#define DD 64

// ---------------- scratch (device globals; no allocation allowed) ----------
__device__ __align__(16) unsigned g_Ap[(size_t)BB * NN * (NN / 32)]; // bit-packed A
__device__ float g_dinv[BB * NN];
// ping-pong fp16 feature buffers, row-major [b][j][d], pre-scaled by dinv_j
__device__ __align__(16) __half g_tb[2][(size_t)BB * NN * DD];

// ---------------- threefry2x32 (Random123 / JAX) ---------------------------
__host__ __device__ constexpr unsigned rotl32(unsigned x, int r) {
  return (x << r) | (x >> (32 - r));
}

__host__ __device__ constexpr void tf2x32(unsigned k0, unsigned k1,
                                          unsigned& x0, unsigned& x1) {
  unsigned k2 = k0 ^ k1 ^ 0x1BD11BDAu;
  x0 += k0; x1 += k1;
  x0+=x1; x1=rotl32(x1,13); x1^=x0;
  x0+=x1; x1=rotl32(x1,15); x1^=x0;
  x0+=x1; x1=rotl32(x1,26); x1^=x0;
  x0+=x1; x1=rotl32(x1, 6); x1^=x0;
  x0+=k1; x1+=k2+1u;
  x0+=x1; x1=rotl32(x1,17); x1^=x0;
  x0+=x1; x1=rotl32(x1,29); x1^=x0;
  x0+=x1; x1=rotl32(x1,16); x1^=x0;
  x0+=x1; x1=rotl32(x1,24); x1^=x0;
  x0+=k2; x1+=k0+2u;
  x0+=x1; x1=rotl32(x1,13); x1^=x0;
  x0+=x1; x1=rotl32(x1,15); x1^=x0;
  x0+=x1; x1=rotl32(x1,26); x1^=x0;
  x0+=x1; x1=rotl32(x1, 6); x1^=x0;
  x0+=k0; x1+=k1+3u;
  x0+=x1; x1=rotl32(x1,17); x1^=x0;
  x0+=x1; x1=rotl32(x1,29); x1^=x0;
  x0+=x1; x1=rotl32(x1,16); x1^=x0;
  x0+=x1; x1=rotl32(x1,24); x1^=x0;
  x0+=k1; x1+=k2+4u;
  x0+=x1; x1=rotl32(x1,13); x1^=x0;
  x0+=x1; x1=rotl32(x1,15); x1^=x0;
  x0+=x1; x1=rotl32(x1,26); x1^=x0;
  x0+=x1; x1=rotl32(x1, 6); x1^=x0;
  x0+=k2; x1+=k0+5u;
}

struct KeyPair { unsigned a, b; };
__host__ __device__ constexpr KeyPair derive_key(unsigned ctr) {
  unsigned x0 = 0u, x1 = ctr;
  tf2x32(0u, 42u, x0, x1);
  return KeyPair{x0, x1};
}
constexpr KeyPair cK1 = derive_key(0u);
constexpr KeyPair cK2 = derive_key(1u);

__device__ __forceinline__ float drop_apply(float v, unsigned idx,
                                            unsigned ka, unsigned kb) {
  unsigned y0 = 0u, y1 = idx;
  tf2x32(ka, kb, y0, y1);
  unsigned bits = y0 ^ y1;
  float u = __uint_as_float((bits >> 9) | 0x3f800000u) - 1.0f;
  return (u < 0.8f) ? v * 1.25f : 0.0f;
}

// ---------------- mma helpers (baseline sm_103-safe) ------------------------
__device__ __forceinline__ unsigned smem_u32(const void* p) {
  unsigned r;
  asm("{ .reg .u64 t; cvta.to.shared.u64 t, %1; cvt.u32.u64 %0, t; }"
      : "=r"(r) : "l"(p));
  return r;
}
__device__ __forceinline__ void ldsm_x4(unsigned* r, const void* p) {
  unsigned addr = smem_u32(p);
  asm volatile("ldmatrix.sync.aligned.m8n8.x4.shared.b16 {%0,%1,%2,%3}, [%4];"
               : "=r"(r[0]), "=r"(r[1]), "=r"(r[2]), "=r"(r[3]) : "r"(addr));
}
__device__ __forceinline__ void ldsm_x4_t(unsigned* r, const void* p) {
  unsigned addr = smem_u32(p);
  asm volatile("ldmatrix.sync.aligned.m8n8.x4.trans.shared.b16 {%0,%1,%2,%3}, [%4];"
               : "=r"(r[0]), "=r"(r[1]), "=r"(r[2]), "=r"(r[3]) : "r"(addr));
}
__device__ __forceinline__ void mma16816(float* c, const unsigned* a,
                                         unsigned b0, unsigned b1) {
  asm volatile(
      "mma.sync.aligned.m16n8k16.row.col.f32.f16.f16.f32 "
      "{%0,%1,%2,%3}, {%4,%5,%6,%7}, {%8,%9}, {%0,%1,%2,%3};"
      : "+f"(c[0]), "+f"(c[1]), "+f"(c[2]), "+f"(c[3])
      : "r"(a[0]), "r"(a[1]), "r"(a[2]), "r"(a[3]), "r"(b0), "r"(b1));
}

// expand 8 bits -> 8 fp16 (0/1) packed in uint4
__device__ __forceinline__ uint4 expand8(unsigned b) {
  uint4 v;
  v.x = ((b & 0x01u)     | ((b & 0x02u) << 15)) * 0x3C00u;
  v.y = (((b >> 2) & 1u) | ((b & 0x08u) << 13)) * 0x3C00u;
  v.z = (((b >> 4) & 1u) | ((b & 0x20u) << 11)) * 0x3C00u;
  v.w = (((b >> 6) & 1u) | ((b & 0x80u) <<  9)) * 0x3C00u;
  return v;
}

// ---------------- kernel 1: degrees + bit-packed A --------------------------
__global__ __launch_bounds__(128) void prep_kernel(const int* __restrict__ adj) {
  int bi = blockIdx.x;
  int i  = bi & (NN - 1);
  const int4* row4 = (const int4*)(adj + (size_t)bi * NN);
  int tid = threadIdx.x;
  unsigned word = 0u;
#pragma unroll
  for (int s = 0; s < 8; s++) {
    int4 v = row4[tid * 8 + s];
    unsigned m = (unsigned)(v.x != 0) | ((unsigned)(v.y != 0) << 1) |
                 ((unsigned)(v.z != 0) << 2) | ((unsigned)(v.w != 0) << 3);
    word |= m << (s * 4);
  }
  if ((i >> 5) == tid) word |= 1u << (i & 31);
  g_Ap[(size_t)bi * 128 + tid] = word;

  int cnt = __popc(word);
  __shared__ int red[4];
  int wsum = __reduce_add_sync(0xffffffffu, cnt);
  if ((tid & 31) == 0) red[tid >> 5] = wsum;
  __syncthreads();
  if (tid == 0) {
    int total = red[0] + red[1] + red[2] + red[3];
    g_dinv[bi] = rsqrtf((float)total);
  }
}

// ---------------- kernel 1b: t0[j][d] = fp16(dinv_j * x[j][d]) --------------
__global__ __launch_bounds__(256) void scalex_kernel(const float* __restrict__ x) {
  int idx = blockIdx.x * 256 + threadIdx.x;      // one per 8 elements
  size_t base = (size_t)idx * 8;
  int j = (int)(base >> 6);                       // flat row b*NN+j
  float dv = g_dinv[j];
  float4 v0 = *(const float4*)&x[base];
  float4 v1 = *(const float4*)&x[base + 4];
  __half h[8];
  h[0] = __float2half(v0.x * dv); h[1] = __float2half(v0.y * dv);
  h[2] = __float2half(v0.z * dv); h[3] = __float2half(v0.w * dv);
  h[4] = __float2half(v1.x * dv); h[5] = __float2half(v1.y * dv);
  h[6] = __float2half(v1.z * dv); h[7] = __float2half(v1.w * dv);
  *(uint4*)&g_tb[0][base] = *(uint4*)h;
}

// ---------------- kernel 2: fused  out = dinv_i*(A@t)@W + b [; elu; drop] ---
// M-tile = 64, K-chunk = 128. 8 warps in (m2, k2, n2): warp = M32 x N32 x K64.
#define AS_STRIDE 136
#define BS_STRIDE 72
#define OFF_B0 0
#define OFF_B1 18432
#define OFF_A0 36864
#define OFF_A1 54272
#define OFF_WHI 71680
#define OFF_WLO 80896
#define AGG_DYN 90112

__global__ __launch_bounds__(256, 2) void agg_kernel(
    const float* __restrict__ Wm, const float* __restrict__ bias,
    float* __restrict__ outp, int tin_sel,
    unsigned ka, unsigned kb, int do_drop) {
  extern __shared__ __align__(16) char smem[];
  __half* Whi = (__half*)(smem + OFF_WHI);
  __half* Wlo = (__half*)(smem + OFF_WLO);

  int tid = threadIdx.x, wid = tid >> 5, lane = tid & 31;
  // mainloop warp grid: m2 x k2 x n2
  int wm = wid >> 2, kg = (wid >> 1) & 1, wn = wid & 1;
  int b = blockIdx.y, i0 = blockIdx.x * 64;

  // W hi/lo split
#pragma unroll
  for (int s = 0; s < 16; s++) {
    int idx = tid + 256 * s;
    int r = idx >> 6, c = idx & 63;
    float w = Wm[idx];
    __half hh = __float2half(w);
    Whi[r * BS_STRIDE + c] = hh;
    Wlo[r * BS_STRIDE + c] = __float2half(w - __half2float(hh));
  }

  const unsigned* Ap = g_Ap + ((size_t)b * NN + i0) * 128;
  const __half* tin = g_tb[tin_sel] + (size_t)b * NN * DD;
  __half* tout = g_tb[tin_sel ^ 1] + (size_t)b * NN * DD;

  // fill mapping: A -> 64 rows x 4 words, one word per thread
  int arow = tid & 63;
  int awo  = tid >> 6;             // word 0..3 within chunk

  float acc[2][4][4];
#pragma unroll
  for (int mt = 0; mt < 2; mt++)
#pragma unroll
    for (int nt = 0; nt < 4; nt++)
#pragma unroll
      for (int q = 0; q < 4; q++) acc[mt][nt][q] = 0.0f;

  int lr = lane & 15, lc8 = (lane >> 4) << 3;

  // staged registers
  unsigned aw;
  uint4 bv[4];

  // preload + store chunk 0 into buffer 0
  aw = Ap[(size_t)arow * 128 + awo];
#pragma unroll
  for (int s = 0; s < 4; s++) {
    int q = tid + 256 * s;
    bv[s] = *(const uint4*)&tin[(size_t)(q >> 3) * DD + (q & 7) * 8];
  }
  {
    __half (*As)[AS_STRIDE] = (__half(*)[AS_STRIDE])(smem + OFF_A0);
    __half (*Bs)[BS_STRIDE] = (__half(*)[BS_STRIDE])(smem + OFF_B0);
#pragma unroll
    for (int g8 = 0; g8 < 4; g8++)
      *(uint4*)&As[arow][awo * 32 + g8 * 8] = expand8(aw >> (g8 * 8));
#pragma unroll
    for (int s = 0; s < 4; s++) {
      int q = tid + 256 * s;
      *(uint4*)&Bs[q >> 3][(q & 7) * 8] = bv[s];
    }
  }
  __syncthreads();

  for (int c = 0; c < 32; c++) {
    int cur = c & 1;
    __half (*As)[AS_STRIDE] =
        (__half(*)[AS_STRIDE])(smem + (cur ? OFF_A1 : OFF_A0));
    __half (*Bs)[BS_STRIDE] =
        (__half(*)[BS_STRIDE])(smem + (cur ? OFF_B1 : OFF_B0));
    // issue global loads for chunk c+1 (latency hidden behind MMAs)
    if (c < 31) {
      int kn = (c + 1) * 128;
      aw = Ap[(size_t)arow * 128 + (kn >> 5) + awo];
#pragma unroll
      for (int s = 0; s < 4; s++) {
        int q = tid + 256 * s;
        bv[s] = *(const uint4*)&tin[(size_t)(kn + (q >> 3)) * DD + (q & 7) * 8];
      }
    }
    // MMA on current buffer: warp's K-slice = [kg*64, kg*64+64)
#pragma unroll
    for (int ks = 0; ks < 4; ks++) {
      int kc = kg * 64 + ks * 16;
      unsigned a[2][4], bf[2][4];
#pragma unroll
      for (int mt = 0; mt < 2; mt++)
        ldsm_x4(a[mt], &As[wm * 32 + mt * 16 + lr][kc + lc8]);
#pragma unroll
      for (int nh = 0; nh < 2; nh++)
        ldsm_x4_t(bf[nh], &Bs[kc + lr][wn * 32 + nh * 16 + lc8]);
#pragma unroll
      for (int mt = 0; mt < 2; mt++)
#pragma unroll
        for (int nt = 0; nt < 4; nt++)
          mma16816(acc[mt][nt], a[mt],
                   bf[nt >> 1][(nt & 1) * 2], bf[nt >> 1][(nt & 1) * 2 + 1]);
    }
    // store staged chunk c+1
    if (c < 31) {
      __half (*An)[AS_STRIDE] =
          (__half(*)[AS_STRIDE])(smem + (cur ? OFF_A0 : OFF_A1));
      __half (*Bn)[BS_STRIDE] =
          (__half(*)[BS_STRIDE])(smem + (cur ? OFF_B0 : OFF_B1));
#pragma unroll
      for (int g8 = 0; g8 < 4; g8++)
        *(uint4*)&An[arow][awo * 32 + g8 * 8] = expand8(aw >> (g8 * 8));
#pragma unroll
      for (int s = 0; s < 4; s++) {
        int q = tid + 256 * s;
        *(uint4*)&Bn[q >> 3][(q & 7) * 8] = bv[s];
      }
    }
    __syncthreads();
  }

  // ---- cross-kg reduction + Cs = fp16(dinv_i * C) --------------------------
  float* Rs = (float*)(smem + OFF_B0);          // 64 x 68 fp32 (17408 B)
  __half* Cs = (__half*)(smem + OFF_A0);        // 64 x 72 fp16 (9216 B)
  int g = lane >> 2, tig = lane & 3;

  if (kg == 1) {
#pragma unroll
    for (int mt = 0; mt < 2; mt++)
#pragma unroll
      for (int hr = 0; hr < 2; hr++) {
        int il = wm * 32 + mt * 16 + g + hr * 8;
#pragma unroll
        for (int nt = 0; nt < 4; nt++) {
          int col = wn * 32 + nt * 8 + tig * 2;
          *(float2*)&Rs[il * 68 + col] =
              make_float2(acc[mt][nt][hr * 2], acc[mt][nt][hr * 2 + 1]);
        }
      }
  }
  __syncthreads();
  if (kg == 0) {
#pragma unroll
    for (int mt = 0; mt < 2; mt++)
#pragma unroll
      for (int hr = 0; hr < 2; hr++) {
        int il = wm * 32 + mt * 16 + g + hr * 8;
        float dv = g_dinv[b * NN + i0 + il];
#pragma unroll
        for (int nt = 0; nt < 4; nt++) {
          int col = wn * 32 + nt * 8 + tig * 2;
          float2 r = *(float2*)&Rs[il * 68 + col];
          __half2 hv =
              __floats2half2_rn((acc[mt][nt][hr * 2] + r.x) * dv,
                                (acc[mt][nt][hr * 2 + 1] + r.y) * dv);
          *(__half2*)&Cs[il * BS_STRIDE + col] = hv;
        }
      }
  }
  __syncthreads();

  // W-multiply: D = Cs @ (Whi + Wlo); warp grid m2 x n4, tile M32 x N16, K=64
  int warp_m = wid >> 2, warp_n = wid & 3;
  float acc2[2][2][4];
#pragma unroll
  for (int mt = 0; mt < 2; mt++)
#pragma unroll
    for (int nt = 0; nt < 2; nt++)
#pragma unroll
      for (int q = 0; q < 4; q++) acc2[mt][nt][q] = 0.0f;

#pragma unroll
  for (int ks = 0; ks < 4; ks++) {
    unsigned a2[2][4], bh[4], bl[4];
#pragma unroll
    for (int mt = 0; mt < 2; mt++)
      ldsm_x4(a2[mt], &Cs[(warp_m * 32 + mt * 16 + lr) * BS_STRIDE + ks * 16 + lc8]);
    ldsm_x4_t(bh, &Whi[(ks * 16 + lr) * BS_STRIDE + warp_n * 16 + lc8]);
    ldsm_x4_t(bl, &Wlo[(ks * 16 + lr) * BS_STRIDE + warp_n * 16 + lc8]);
#pragma unroll
    for (int mt = 0; mt < 2; mt++)
#pragma unroll
      for (int nt = 0; nt < 2; nt++) {
        mma16816(acc2[mt][nt], a2[mt], bh[nt * 2], bh[nt * 2 + 1]);
        mma16816(acc2[mt][nt], a2[mt], bl[nt * 2], bl[nt * 2 + 1]);
      }
  }

  // final epilogue
#pragma unroll
  for (int mt = 0; mt < 2; mt++) {
#pragma unroll
    for (int hr = 0; hr < 2; hr++) {
      int i = i0 + warp_m * 32 + mt * 16 + g + hr * 8;
      float dv = g_dinv[b * NN + i];
#pragma unroll
      for (int nt = 0; nt < 2; nt++) {
#pragma unroll
        for (int c2 = 0; c2 < 2; c2++) {
          int col = warp_n * 16 + nt * 8 + tig * 2 + c2;
          float v = acc2[mt][nt][hr * 2 + c2] + __ldg(&bias[col]);
          unsigned idx = ((unsigned)(b * NN + i)) * 64u + (unsigned)col;
          if (do_drop) {
            v = (v > 0.0f) ? v : expm1f(v);      // ELU
            v = drop_apply(v, idx, ka, kb);      // JAX threefry dropout
            tout[(size_t)i * DD + col] = __float2half(v * dv);
          } else {
            outp[idx] = v;
          }
        }
      }
    }
  }
}

// ---------------- launch ----------------------------------------------------
extern "C" void kernel_launch(void* const* d_in, const int* in_sizes, int n_in,
                              void* d_out, int out_size) {
  const float* x  = (const float*)d_in[0];
  const int*   adj= (const int*)d_in[1];
  const float* W1 = (const float*)d_in[2];
  const float* b1 = (const float*)d_in[3];
  const float* W2 = (const float*)d_in[4];
  const float* b2 = (const float*)d_in[5];
  const float* W3 = (const float*)d_in[6];
  const float* b3 = (const float*)d_in[7];
  float* out = (float*)d_out;

  (void)in_sizes; (void)n_in; (void)out_size;

  cudaFuncSetAttribute(agg_kernel, cudaFuncAttributeMaxDynamicSharedMemorySize,
                       AGG_DYN);

  prep_kernel<<<BB * NN, 128>>>(adj);
  scalex_kernel<<<(BB * NN * DD) / 8 / 256, 256>>>(x);

  dim3 agrid(NN / 64, BB);
  agg_kernel<<<agrid, 256, AGG_DYN>>>(W1, b1, nullptr, 0, cK1.a, cK1.b, 1);
  agg_kernel<<<agrid, 256, AGG_DYN>>>(W2, b2, nullptr, 1, cK2.a, cK2.b, 1);
  agg_kernel<<<agrid, 256, AGG_DYN>>>(W3, b3, out, 0, 0u, 0u, 0);
}

// round 11
// speedup vs baseline: 2.2481x; 1.0162x over previous
#include <cuda_runtime.h>
#include <cuda_fp16.h>

#define BB 4
#define NN 4096
#define DD 64

// ---------------- scratch (device globals; no allocation allowed) ----------
__device__ __align__(16) unsigned g_Ap[(size_t)BB * NN * (NN / 32)]; // bit-packed A
__device__ float g_dinv[BB * NN];
// ping-pong fp16 feature buffers, row-major [b][j][d], pre-scaled by dinv_j
__device__ __align__(16) __half g_tb[2][(size_t)BB * NN * DD];

// ---------------- threefry2x32 (Random123 / JAX) ---------------------------
__host__ __device__ constexpr unsigned rotl32(unsigned x, int r) {
  return (x << r) | (x >> (32 - r));
}

__host__ __device__ constexpr void tf2x32(unsigned k0, unsigned k1,
                                          unsigned& x0, unsigned& x1) {
  unsigned k2 = k0 ^ k1 ^ 0x1BD11BDAu;
  x0 += k0; x1 += k1;
  x0+=x1; x1=rotl32(x1,13); x1^=x0;
  x0+=x1; x1=rotl32(x1,15); x1^=x0;
  x0+=x1; x1=rotl32(x1,26); x1^=x0;
  x0+=x1; x1=rotl32(x1, 6); x1^=x0;
  x0+=k1; x1+=k2+1u;
  x0+=x1; x1=rotl32(x1,17); x1^=x0;
  x0+=x1; x1=rotl32(x1,29); x1^=x0;
  x0+=x1; x1=rotl32(x1,16); x1^=x0;
  x0+=x1; x1=rotl32(x1,24); x1^=x0;
  x0+=k2; x1+=k0+2u;
  x0+=x1; x1=rotl32(x1,13); x1^=x0;
  x0+=x1; x1=rotl32(x1,15); x1^=x0;
  x0+=x1; x1=rotl32(x1,26); x1^=x0;
  x0+=x1; x1=rotl32(x1, 6); x1^=x0;
  x0+=k0; x1+=k1+3u;
  x0+=x1; x1=rotl32(x1,17); x1^=x0;
  x0+=x1; x1=rotl32(x1,29); x1^=x0;
  x0+=x1; x1=rotl32(x1,16); x1^=x0;
  x0+=x1; x1=rotl32(x1,24); x1^=x0;
  x0+=k1; x1+=k2+4u;
  x0+=x1; x1=rotl32(x1,13); x1^=x0;
  x0+=x1; x1=rotl32(x1,15); x1^=x0;
  x0+=x1; x1=rotl32(x1,26); x1^=x0;
  x0+=x1; x1=rotl32(x1, 6); x1^=x0;
  x0+=k2; x1+=k0+5u;
}

struct KeyPair { unsigned a, b; };
__host__ __device__ constexpr KeyPair derive_key(unsigned ctr) {
  unsigned x0 = 0u, x1 = ctr;
  tf2x32(0u, 42u, x0, x1);
  return KeyPair{x0, x1};
}
constexpr KeyPair cK1 = derive_key(0u);
constexpr KeyPair cK2 = derive_key(1u);

__device__ __forceinline__ float drop_apply(float v, unsigned idx,
                                            unsigned ka, unsigned kb) {
  unsigned y0 = 0u, y1 = idx;
  tf2x32(ka, kb, y0, y1);
  unsigned bits = y0 ^ y1;
  float u = __uint_as_float((bits >> 9) | 0x3f800000u) - 1.0f;
  return (u < 0.8f) ? v * 1.25f : 0.0f;
}

// ---------------- mma helpers (baseline sm_103-safe) ------------------------
__device__ __forceinline__ unsigned smem_u32(const void* p) {
  unsigned r;
  asm("{ .reg .u64 t; cvta.to.shared.u64 t, %1; cvt.u32.u64 %0, t; }"
      : "=r"(r) : "l"(p));
  return r;
}
__device__ __forceinline__ void ldsm_x4(unsigned* r, const void* p) {
  unsigned addr = smem_u32(p);
  asm volatile("ldmatrix.sync.aligned.m8n8.x4.shared.b16 {%0,%1,%2,%3}, [%4];"
               : "=r"(r[0]), "=r"(r[1]), "=r"(r[2]), "=r"(r[3]) : "r"(addr));
}
__device__ __forceinline__ void ldsm_x4_t(unsigned* r, const void* p) {
  unsigned addr = smem_u32(p);
  asm volatile("ldmatrix.sync.aligned.m8n8.x4.trans.shared.b16 {%0,%1,%2,%3}, [%4];"
               : "=r"(r[0]), "=r"(r[1]), "=r"(r[2]), "=r"(r[3]) : "r"(addr));
}
__device__ __forceinline__ void mma16816(float* c, const unsigned* a,
                                         unsigned b0, unsigned b1) {
  asm volatile(
      "mma.sync.aligned.m16n8k16.row.col.f32.f16.f16.f32 "
      "{%0,%1,%2,%3}, {%4,%5,%6,%7}, {%8,%9}, {%0,%1,%2,%3};"
      : "+f"(c[0]), "+f"(c[1]), "+f"(c[2]), "+f"(c[3])
      : "r"(a[0]), "r"(a[1]), "r"(a[2]), "r"(a[3]), "r"(b0), "r"(b1));
}

// expand 8 bits -> 8 fp16 (0/1) packed in uint4
__device__ __forceinline__ uint4 expand8(unsigned b) {
  uint4 v;
  v.x = ((b & 0x01u)     | ((b & 0x02u) << 15)) * 0x3C00u;
  v.y = (((b >> 2) & 1u) | ((b & 0x08u) << 13)) * 0x3C00u;
  v.z = (((b >> 4) & 1u) | ((b & 0x20u) << 11)) * 0x3C00u;
  v.w = (((b >> 6) & 1u) | ((b & 0x80u) <<  9)) * 0x3C00u;
  return v;
}

// ---------------- kernel 1: degrees + bit-packed A --------------------------
__global__ __launch_bounds__(128) void prep_kernel(const int* __restrict__ adj) {
  int bi = blockIdx.x;
  int i  = bi & (NN - 1);
  const int4* row4 = (const int4*)(adj + (size_t)bi * NN);
  int tid = threadIdx.x;
  unsigned word = 0u;
#pragma unroll
  for (int s = 0; s < 8; s++) {
    int4 v = row4[tid * 8 + s];
    unsigned m = (unsigned)(v.x != 0) | ((unsigned)(v.y != 0) << 1) |
                 ((unsigned)(v.z != 0) << 2) | ((unsigned)(v.w != 0) << 3);
    word |= m << (s * 4);
  }
  if ((i >> 5) == tid) word |= 1u << (i & 31);
  g_Ap[(size_t)bi * 128 + tid] = word;

  int cnt = __popc(word);
  __shared__ int red[4];
  int wsum = __reduce_add_sync(0xffffffffu, cnt);
  if ((tid & 31) == 0) red[tid >> 5] = wsum;
  __syncthreads();
  if (tid == 0) {
    int total = red[0] + red[1] + red[2] + red[3];
    g_dinv[bi] = rsqrtf((float)total);
  }
}

// ---------------- kernel 1b: t0[j][d] = fp16(dinv_j * x[j][d]) --------------
__global__ __launch_bounds__(256) void scalex_kernel(const float* __restrict__ x) {
  int idx = blockIdx.x * 256 + threadIdx.x;      // one per 8 elements
  size_t base = (size_t)idx * 8;
  int j = (int)(base >> 6);                       // flat row b*NN+j
  float dv = g_dinv[j];
  float4 v0 = *(const float4*)&x[base];
  float4 v1 = *(const float4*)&x[base + 4];
  __half h[8];
  h[0] = __float2half(v0.x * dv); h[1] = __float2half(v0.y * dv);
  h[2] = __float2half(v0.z * dv); h[3] = __float2half(v0.w * dv);
  h[4] = __float2half(v1.x * dv); h[5] = __float2half(v1.y * dv);
  h[6] = __float2half(v1.z * dv); h[7] = __float2half(v1.w * dv);
  *(uint4*)&g_tb[0][base] = *(uint4*)h;
}

// ---------------- kernel 2: fused  out = dinv_i*(A@t)@W + b [; elu; drop] ---
// M-tile = 128, K-chunk = 128, 512 threads, warp grid (m4, k2, n2).
#define AS_STRIDE 136
#define BS_STRIDE 72
#define OFF_A0 0
#define OFF_A1 34816
#define OFF_B0 69632
#define OFF_B1 88064
#define OFF_WHI 106496
#define OFF_WLO 115712
#define AGG_DYN 124928

__global__ __launch_bounds__(512, 1) void agg_kernel(
    const float* __restrict__ Wm, const float* __restrict__ bias,
    float* __restrict__ outp, int tin_sel,
    unsigned ka, unsigned kb, int do_drop) {
  extern __shared__ __align__(16) char smem[];
  __half* Whi = (__half*)(smem + OFF_WHI);
  __half* Wlo = (__half*)(smem + OFF_WLO);

  int tid = threadIdx.x, wid = tid >> 5, lane = tid & 31;
  // mainloop warp grid: m4 x k2 x n2
  int wm = wid >> 2, kg = (wid >> 1) & 1, wn = wid & 1;
  int b = blockIdx.y, i0 = blockIdx.x * 128;

  // W hi/lo split
#pragma unroll
  for (int s = 0; s < 8; s++) {
    int idx = tid + 512 * s;
    int r = idx >> 6, c = idx & 63;
    float w = Wm[idx];
    __half hh = __float2half(w);
    Whi[r * BS_STRIDE + c] = hh;
    Wlo[r * BS_STRIDE + c] = __float2half(w - __half2float(hh));
  }

  const unsigned* Ap = g_Ap + ((size_t)b * NN + i0) * 128;
  const __half* tin = g_tb[tin_sel] + (size_t)b * NN * DD;
  __half* tout = g_tb[tin_sel ^ 1] + (size_t)b * NN * DD;

  // fill mapping: A -> 128 rows x 4 words, one word per thread
  int arow = tid & 127;
  int awo  = tid >> 7;             // word 0..3 within chunk

  float acc[2][4][4];
#pragma unroll
  for (int mt = 0; mt < 2; mt++)
#pragma unroll
    for (int nt = 0; nt < 4; nt++)
#pragma unroll
      for (int q = 0; q < 4; q++) acc[mt][nt][q] = 0.0f;

  int lr = lane & 15, lc8 = (lane >> 4) << 3;

  // staged registers
  unsigned aw;
  uint4 bv[2];

  // preload + store chunk 0 into buffer 0
  aw = Ap[(size_t)arow * 128 + awo];
#pragma unroll
  for (int s = 0; s < 2; s++) {
    int q = tid + 512 * s;
    bv[s] = *(const uint4*)&tin[(size_t)(q >> 3) * DD + (q & 7) * 8];
  }
  {
    __half (*As)[AS_STRIDE] = (__half(*)[AS_STRIDE])(smem + OFF_A0);
    __half (*Bs)[BS_STRIDE] = (__half(*)[BS_STRIDE])(smem + OFF_B0);
#pragma unroll
    for (int g8 = 0; g8 < 4; g8++)
      *(uint4*)&As[arow][awo * 32 + g8 * 8] = expand8(aw >> (g8 * 8));
#pragma unroll
    for (int s = 0; s < 2; s++) {
      int q = tid + 512 * s;
      *(uint4*)&Bs[q >> 3][(q & 7) * 8] = bv[s];
    }
  }
  __syncthreads();

  for (int c = 0; c < 32; c++) {
    int cur = c & 1;
    __half (*As)[AS_STRIDE] =
        (__half(*)[AS_STRIDE])(smem + (cur ? OFF_A1 : OFF_A0));
    __half (*Bs)[BS_STRIDE] =
        (__half(*)[BS_STRIDE])(smem + (cur ? OFF_B1 : OFF_B0));
    // issue global loads for chunk c+1 (latency hidden behind MMAs)
    if (c < 31) {
      int kn = (c + 1) * 128;
      aw = Ap[(size_t)arow * 128 + (kn >> 5) + awo];
#pragma unroll
      for (int s = 0; s < 2; s++) {
        int q = tid + 512 * s;
        bv[s] = *(const uint4*)&tin[(size_t)(kn + (q >> 3)) * DD + (q & 7) * 8];
      }
    }
    // MMA on current buffer: warp's K-slice = [kg*64, kg*64+64)
#pragma unroll
    for (int ks = 0; ks < 4; ks++) {
      int kc = kg * 64 + ks * 16;
      unsigned a[2][4], bf[2][4];
#pragma unroll
      for (int mt = 0; mt < 2; mt++)
        ldsm_x4(a[mt], &As[wm * 32 + mt * 16 + lr][kc + lc8]);
#pragma unroll
      for (int nh = 0; nh < 2; nh++)
        ldsm_x4_t(bf[nh], &Bs[kc + lr][wn * 32 + nh * 16 + lc8]);
#pragma unroll
      for (int mt = 0; mt < 2; mt++)
#pragma unroll
        for (int nt = 0; nt < 4; nt++)
          mma16816(acc[mt][nt], a[mt],
                   bf[nt >> 1][(nt & 1) * 2], bf[nt >> 1][(nt & 1) * 2 + 1]);
    }
    // store staged chunk c+1
    if (c < 31) {
      __half (*An)[AS_STRIDE] =
          (__half(*)[AS_STRIDE])(smem + (cur ? OFF_A0 : OFF_A1));
      __half (*Bn)[BS_STRIDE] =
          (__half(*)[BS_STRIDE])(smem + (cur ? OFF_B0 : OFF_B1));
#pragma unroll
      for (int g8 = 0; g8 < 4; g8++)
        *(uint4*)&An[arow][awo * 32 + g8 * 8] = expand8(aw >> (g8 * 8));
#pragma unroll
      for (int s = 0; s < 2; s++) {
        int q = tid + 512 * s;
        *(uint4*)&Bn[q >> 3][(q & 7) * 8] = bv[s];
      }
    }
    __syncthreads();
  }

  // ---- cross-kg reduction + Cs = fp16(dinv_i * C) --------------------------
  float* Rs = (float*)(smem + OFF_A0);          // 128 x 68 fp32 (34816 B)
  __half* Cs = (__half*)(smem + OFF_B0);        // 128 x 72 fp16 (18432 B)
  int g = lane >> 2, tig = lane & 3;

  if (kg == 1) {
#pragma unroll
    for (int mt = 0; mt < 2; mt++)
#pragma unroll
      for (int hr = 0; hr < 2; hr++) {
        int il = wm * 32 + mt * 16 + g + hr * 8;
#pragma unroll
        for (int nt = 0; nt < 4; nt++) {
          int col = wn * 32 + nt * 8 + tig * 2;
          *(float2*)&Rs[il * 68 + col] =
              make_float2(acc[mt][nt][hr * 2], acc[mt][nt][hr * 2 + 1]);
        }
      }
  }
  __syncthreads();
  if (kg == 0) {
#pragma unroll
    for (int mt = 0; mt < 2; mt++)
#pragma unroll
      for (int hr = 0; hr < 2; hr++) {
        int il = wm * 32 + mt * 16 + g + hr * 8;
        float dv = g_dinv[b * NN + i0 + il];
#pragma unroll
        for (int nt = 0; nt < 4; nt++) {
          int col = wn * 32 + nt * 8 + tig * 2;
          float2 r = *(float2*)&Rs[il * 68 + col];
          __half2 hv =
              __floats2half2_rn((acc[mt][nt][hr * 2] + r.x) * dv,
                                (acc[mt][nt][hr * 2 + 1] + r.y) * dv);
          *(__half2*)&Cs[il * BS_STRIDE + col] = hv;
        }
      }
  }
  __syncthreads();

  // W-multiply: D = Cs @ (Whi + Wlo); warp grid m4 x n4, tile M32 x N16, K=64
  int warp_m = wid >> 2, warp_n = wid & 3;
  float acc2[2][2][4];
#pragma unroll
  for (int mt = 0; mt < 2; mt++)
#pragma unroll
    for (int nt = 0; nt < 2; nt++)
#pragma unroll
      for (int q = 0; q < 4; q++) acc2[mt][nt][q] = 0.0f;

#pragma unroll
  for (int ks = 0; ks < 4; ks++) {
    unsigned a2[2][4], bh[4], bl[4];
#pragma unroll
    for (int mt = 0; mt < 2; mt++)
      ldsm_x4(a2[mt], &Cs[(warp_m * 32 + mt * 16 + lr) * BS_STRIDE + ks * 16 + lc8]);
    ldsm_x4_t(bh, &Whi[(ks * 16 + lr) * BS_STRIDE + warp_n * 16 + lc8]);
    ldsm_x4_t(bl, &Wlo[(ks * 16 + lr) * BS_STRIDE + warp_n * 16 + lc8]);
#pragma unroll
    for (int mt = 0; mt < 2; mt++)
#pragma unroll
      for (int nt = 0; nt < 2; nt++) {
        mma16816(acc2[mt][nt], a2[mt], bh[nt * 2], bh[nt * 2 + 1]);
        mma16816(acc2[mt][nt], a2[mt], bl[nt * 2], bl[nt * 2 + 1]);
      }
  }

  // final epilogue
#pragma unroll
  for (int mt = 0; mt < 2; mt++) {
#pragma unroll
    for (int hr = 0; hr < 2; hr++) {
      int i = i0 + warp_m * 32 + mt * 16 + g + hr * 8;
      float dv = g_dinv[b * NN + i];
#pragma unroll
      for (int nt = 0; nt < 2; nt++) {
#pragma unroll
        for (int c2 = 0; c2 < 2; c2++) {
          int col = warp_n * 16 + nt * 8 + tig * 2 + c2;
          float v = acc2[mt][nt][hr * 2 + c2] + __ldg(&bias[col]);
          unsigned idx = ((unsigned)(b * NN + i)) * 64u + (unsigned)col;
          if (do_drop) {
            v = (v > 0.0f) ? v : expm1f(v);      // ELU
            v = drop_apply(v, idx, ka, kb);      // JAX threefry dropout
            tout[(size_t)i * DD + col] = __float2half(v * dv);
          } else {
            outp[idx] = v;
          }
        }
      }
    }
  }
}

// ---------------- launch ----------------------------------------------------
extern "C" void kernel_launch(void* const* d_in, const int* in_sizes, int n_in,
                              void* d_out, int out_size) {
  const float* x  = (const float*)d_in[0];
  const int*   adj= (const int*)d_in[1];
  const float* W1 = (const float*)d_in[2];
  const float* b1 = (const float*)d_in[3];
  const float* W2 = (const float*)d_in[4];
  const float* b2 = (const float*)d_in[5];
  const float* W3 = (const float*)d_in[6];
  const float* b3 = (const float*)d_in[7];
  float* out = (float*)d_out;

  (void)in_sizes; (void)n_in; (void)out_size;

  cudaFuncSetAttribute(agg_kernel, cudaFuncAttributeMaxDynamicSharedMemorySize,
                       AGG_DYN);

  prep_kernel<<<BB * NN, 128>>>(adj);
  scalex_kernel<<<(BB * NN * DD) / 8 / 256, 256>>>(x);

  dim3 agrid(NN / 128, BB);
  agg_kernel<<<agrid, 512, AGG_DYN>>>(W1, b1, nullptr, 0, cK1.a, cK1.b, 1);
  agg_kernel<<<agrid, 512, AGG_DYN>>>(W2, b2, nullptr, 1, cK2.a, cK2.b, 1);
  agg_kernel<<<agrid, 512, AGG_DYN>>>(W3, b3, out, 0, 0u, 0u, 0);
}

// round 15
// speedup vs baseline: 2.4625x; 1.0954x over previous
#include <cuda_runtime.h>
#include <cuda_fp16.h>

#define BB 4
#define NN 4096
#define DD 64

// ---------------- scratch (device globals; no allocation allowed) ----------
__device__ __align__(16) unsigned g_Ap[(size_t)BB * NN * (NN / 32)]; // bit-packed A
__device__ float g_dinv[BB * NN];
// ping-pong fp16 feature buffers, row-major [b][j][d], pre-scaled by dinv_j
__device__ __align__(16) __half g_tb[2][(size_t)BB * NN * DD];

// ---------------- threefry2x32 (Random123 / JAX) ---------------------------
__host__ __device__ constexpr unsigned rotl32(unsigned x, int r) {
  return (x << r) | (x >> (32 - r));
}

__host__ __device__ constexpr void tf2x32(unsigned k0, unsigned k1,
                                          unsigned& x0, unsigned& x1) {
  unsigned k2 = k0 ^ k1 ^ 0x1BD11BDAu;
  x0 += k0; x1 += k1;
  x0+=x1; x1=rotl32(x1,13); x1^=x0;
  x0+=x1; x1=rotl32(x1,15); x1^=x0;
  x0+=x1; x1=rotl32(x1,26); x1^=x0;
  x0+=x1; x1=rotl32(x1, 6); x1^=x0;
  x0+=k1; x1+=k2+1u;
  x0+=x1; x1=rotl32(x1,17); x1^=x0;
  x0+=x1; x1=rotl32(x1,29); x1^=x0;
  x0+=x1; x1=rotl32(x1,16); x1^=x0;
  x0+=x1; x1=rotl32(x1,24); x1^=x0;
  x0+=k2; x1+=k0+2u;
  x0+=x1; x1=rotl32(x1,13); x1^=x0;
  x0+=x1; x1=rotl32(x1,15); x1^=x0;
  x0+=x1; x1=rotl32(x1,26); x1^=x0;
  x0+=x1; x1=rotl32(x1, 6); x1^=x0;
  x0+=k0; x1+=k1+3u;
  x0+=x1; x1=rotl32(x1,17); x1^=x0;
  x0+=x1; x1=rotl32(x1,29); x1^=x0;
  x0+=x1; x1=rotl32(x1,16); x1^=x0;
  x0+=x1; x1=rotl32(x1,24); x1^=x0;
  x0+=k1; x1+=k2+4u;
  x0+=x1; x1=rotl32(x1,13); x1^=x0;
  x0+=x1; x1=rotl32(x1,15); x1^=x0;
  x0+=x1; x1=rotl32(x1,26); x1^=x0;
  x0+=x1; x1=rotl32(x1, 6); x1^=x0;
  x0+=k2; x1+=k0+5u;
}

struct KeyPair { unsigned a, b; };
__host__ __device__ constexpr KeyPair derive_key(unsigned ctr) {
  unsigned x0 = 0u, x1 = ctr;
  tf2x32(0u, 42u, x0, x1);
  return KeyPair{x0, x1};
}
constexpr KeyPair cK1 = derive_key(0u);
constexpr KeyPair cK2 = derive_key(1u);

__device__ __forceinline__ float drop_apply(float v, unsigned idx,
                                            unsigned ka, unsigned kb) {
  unsigned y0 = 0u, y1 = idx;
  tf2x32(ka, kb, y0, y1);
  unsigned bits = y0 ^ y1;
  float u = __uint_as_float((bits >> 9) | 0x3f800000u) - 1.0f;
  return (u < 0.8f) ? v * 1.25f : 0.0f;
}

// ---------------- mma helpers (baseline sm_103-safe) ------------------------
__device__ __forceinline__ unsigned smem_u32(const void* p) {
  unsigned r;
  asm("{ .reg .u64 t; cvta.to.shared.u64 t, %1; cvt.u32.u64 %0, t; }"
      : "=r"(r) : "l"(p));
  return r;
}
__device__ __forceinline__ void ldsm_x4(unsigned* r, const void* p) {
  unsigned addr = smem_u32(p);
  asm volatile("ldmatrix.sync.aligned.m8n8.x4.shared.b16 {%0,%1,%2,%3}, [%4];"
               : "=r"(r[0]), "=r"(r[1]), "=r"(r[2]), "=r"(r[3]) : "r"(addr));
}
__device__ __forceinline__ void ldsm_x4_t(unsigned* r, const void* p) {
  unsigned addr = smem_u32(p);
  asm volatile("ldmatrix.sync.aligned.m8n8.x4.trans.shared.b16 {%0,%1,%2,%3}, [%4];"
               : "=r"(r[0]), "=r"(r[1]), "=r"(r[2]), "=r"(r[3]) : "r"(addr));
}
__device__ __forceinline__ void mma16816(float* c, const unsigned* a,
                                         unsigned b0, unsigned b1) {
  asm volatile(
      "mma.sync.aligned.m16n8k16.row.col.f32.f16.f16.f32 "
      "{%0,%1,%2,%3}, {%4,%5,%6,%7}, {%8,%9}, {%0,%1,%2,%3};"
      : "+f"(c[0]), "+f"(c[1]), "+f"(c[2]), "+f"(c[3])
      : "r"(a[0]), "r"(a[1]), "r"(a[2]), "r"(a[3]), "r"(b0), "r"(b1));
}

// ---------------- kernel 1: degrees + bit-packed A --------------------------
__global__ __launch_bounds__(128) void prep_kernel(const int* __restrict__ adj) {
  int bi = blockIdx.x;
  int i  = bi & (NN - 1);
  const int4* row4 = (const int4*)(adj + (size_t)bi * NN);
  int tid = threadIdx.x;
  unsigned word = 0u;
#pragma unroll
  for (int s = 0; s < 8; s++) {
    int4 v = row4[tid * 8 + s];
    unsigned m = (unsigned)(v.x != 0) | ((unsigned)(v.y != 0) << 1) |
                 ((unsigned)(v.z != 0) << 2) | ((unsigned)(v.w != 0) << 3);
    word |= m << (s * 4);
  }
  if ((i >> 5) == tid) word |= 1u << (i & 31);
  g_Ap[(size_t)bi * 128 + tid] = word;

  int cnt = __popc(word);
  __shared__ int red[4];
  int wsum = __reduce_add_sync(0xffffffffu, cnt);
  if ((tid & 31) == 0) red[tid >> 5] = wsum;
  __syncthreads();
  if (tid == 0) {
    int total = red[0] + red[1] + red[2] + red[3];
    g_dinv[bi] = rsqrtf((float)total);
  }
}

// ---------------- kernel 1b: t0[j][d] = fp16(dinv_j * x[j][d]) --------------
__global__ __launch_bounds__(256) void scalex_kernel(const float* __restrict__ x) {
  int idx = blockIdx.x * 256 + threadIdx.x;      // one per 8 elements
  size_t base = (size_t)idx * 8;
  int j = (int)(base >> 6);                       // flat row b*NN+j
  float dv = g_dinv[j];
  float4 v0 = *(const float4*)&x[base];
  float4 v1 = *(const float4*)&x[base + 4];
  __half h[8];
  h[0] = __float2half(v0.x * dv); h[1] = __float2half(v0.y * dv);
  h[2] = __float2half(v0.z * dv); h[3] = __float2half(v0.w * dv);
  h[4] = __float2half(v1.x * dv); h[5] = __float2half(v1.y * dv);
  h[6] = __float2half(v1.z * dv); h[7] = __float2half(v1.w * dv);
  *(uint4*)&g_tb[0][base] = *(uint4*)h;
}

// ---------------- kernel 2: fused  out = dinv_i*(A@t)@W + b [; elu; drop] ---
// M-tile = 128, K-chunk = 128, 512 threads, warp grid (m4, k2, n2).
// A never expands to smem: packed words staged (2KB), fragments built in regs
// with the fp16-subnormal trick (bit -> 0x0001 == 2^-24; compensated by
// folding 2^24 into the dinv_i epilogue scale).
#define BS_STRIDE 72
#define OFF_B0 0
#define OFF_B1 18432
#define OFF_AP0 36864
#define OFF_AP1 38912
#define OFF_WHI 40960
#define OFF_WLO 50176
#define OFF_CS  59392
#define AGG_DYN 77824

__global__ __launch_bounds__(512, 1) void agg_kernel(
    const float* __restrict__ Wm, const float* __restrict__ bias,
    float* __restrict__ outp, int tin_sel,
    unsigned ka, unsigned kb, int do_drop) {
  extern __shared__ __align__(16) char smem[];
  __half* Whi = (__half*)(smem + OFF_WHI);
  __half* Wlo = (__half*)(smem + OFF_WLO);

  int tid = threadIdx.x, wid = tid >> 5, lane = tid & 31;
  // mainloop warp grid: m4 x k2 x n2
  int wm = wid >> 2, kg = (wid >> 1) & 1, wn = wid & 1;
  int b = blockIdx.y, i0 = blockIdx.x * 128;

  // W hi/lo split
#pragma unroll
  for (int s = 0; s < 8; s++) {
    int idx = tid + 512 * s;
    int r = idx >> 6, c = idx & 63;
    float w = Wm[idx];
    __half hh = __float2half(w);
    Whi[r * BS_STRIDE + c] = hh;
    Wlo[r * BS_STRIDE + c] = __float2half(w - __half2float(hh));
  }

  const unsigned* Ap = g_Ap + ((size_t)b * NN + i0) * 128;
  const __half* tin = g_tb[tin_sel] + (size_t)b * NN * DD;
  __half* tout = g_tb[tin_sel ^ 1] + (size_t)b * NN * DD;

  // packed-A fill mapping: 4 threads per row (word = tid&3), row = tid>>2
  int prow = tid >> 2;
  int pwo  = tid & 3;

  float acc[2][4][4];
#pragma unroll
  for (int mt = 0; mt < 2; mt++)
#pragma unroll
    for (int nt = 0; nt < 4; nt++)
#pragma unroll
      for (int q = 0; q < 4; q++) acc[mt][nt][q] = 0.0f;

  int lr = lane & 15, lc8 = (lane >> 4) << 3;
  // fragment bit positions for this thread
  int t2 = (lane & 3) * 2;
  int s_lo = t2, m_lo = 15 - t2;       // bits t2, t2+1 -> pos 0, 16
  int s_hi = t2 + 8, m_hi = 7 - t2;    // bits t2+8, t2+9 -> pos 0, 16
  // rows whose bits this thread needs (per m-tile)
  int fr0 = wm * 32 + (lane >> 2);     // mt=0 rows: fr0, fr0+8 ; mt=1: +16

  // staged registers
  unsigned apw;
  uint4 bv[2];

  // preload + store chunk 0 into buffer 0
  apw = Ap[(size_t)prow * 128 + pwo];
#pragma unroll
  for (int s = 0; s < 2; s++) {
    int q = tid + 512 * s;
    bv[s] = *(const uint4*)&tin[(size_t)(q >> 3) * DD + (q & 7) * 8];
  }
  {
    unsigned* Apk = (unsigned*)(smem + OFF_AP0);
    __half (*Bs)[BS_STRIDE] = (__half(*)[BS_STRIDE])(smem + OFF_B0);
    Apk[tid] = apw;                         // layout [row][word], row*16B
#pragma unroll
    for (int s = 0; s < 2; s++) {
      int q = tid + 512 * s;
      *(uint4*)&Bs[q >> 3][(q & 7) * 8] = bv[s];
    }
  }
  __syncthreads();

  for (int c = 0; c < 32; c++) {
    int cur = c & 1;
    char* apbuf = smem + (cur ? OFF_AP1 : OFF_AP0);
    __half (*Bs)[BS_STRIDE] =
        (__half(*)[BS_STRIDE])(smem + (cur ? OFF_B1 : OFF_B0));
    // issue global loads for chunk c+1 (latency hidden behind MMAs)
    if (c < 31) {
      int knw = (c + 1) * 4;
      apw = Ap[(size_t)prow * 128 + knw + pwo];
#pragma unroll
      for (int s = 0; s < 2; s++) {
        int q = tid + 512 * s;
        bv[s] = *(const uint4*)&tin[(size_t)((c + 1) * 128 + (q >> 3)) * DD +
                                    (q & 7) * 8];
      }
    }
    // pull this warp's packed K64 slice for its 4 fragment rows
    uint2 w2[2][2];
#pragma unroll
    for (int mt = 0; mt < 2; mt++) {
      int ra = fr0 + mt * 16;
      w2[mt][0] = *(uint2*)(apbuf + ra * 16 + kg * 8);
      w2[mt][1] = *(uint2*)(apbuf + (ra + 8) * 16 + kg * 8);
    }
    // MMA on current buffer: warp's K-slice = [kg*64, kg*64+64)
#pragma unroll
    for (int ks = 0; ks < 4; ks++) {
      int kc = kg * 64 + ks * 16;
      unsigned bf[2][4];
#pragma unroll
      for (int nh = 0; nh < 2; nh++)
        ldsm_x4_t(bf[nh], &Bs[kc + lr][wn * 32 + nh * 16 + lc8]);
      unsigned a[2][4];
#pragma unroll
      for (int mt = 0; mt < 2; mt++) {
        unsigned wax = (ks >> 1) ? w2[mt][0].y : w2[mt][0].x;
        unsigned wbx = (ks >> 1) ? w2[mt][1].y : w2[mt][1].x;
        unsigned wa = (ks & 1) ? (wax >> 16) : (wax & 0xFFFFu);
        unsigned wb = (ks & 1) ? (wbx >> 16) : (wbx & 0xFFFFu);
        a[mt][0] = ((wa >> s_lo) & 1u) | ((wa << m_lo) & 0x10000u);
        a[mt][1] = ((wb >> s_lo) & 1u) | ((wb << m_lo) & 0x10000u);
        a[mt][2] = ((wa >> s_hi) & 1u) | ((wa << m_hi) & 0x10000u);
        a[mt][3] = ((wb >> s_hi) & 1u) | ((wb << m_hi) & 0x10000u);
      }
#pragma unroll
      for (int mt = 0; mt < 2; mt++)
#pragma unroll
        for (int nt = 0; nt < 4; nt++)
          mma16816(acc[mt][nt], a[mt],
                   bf[nt >> 1][(nt & 1) * 2], bf[nt >> 1][(nt & 1) * 2 + 1]);
    }
    // store staged chunk c+1
    if (c < 31) {
      unsigned* Apn = (unsigned*)(smem + (cur ? OFF_AP0 : OFF_AP1));
      __half (*Bn)[BS_STRIDE] =
          (__half(*)[BS_STRIDE])(smem + (cur ? OFF_B0 : OFF_B1));
      Apn[tid] = apw;
#pragma unroll
      for (int s = 0; s < 2; s++) {
        int q = tid + 512 * s;
        *(uint4*)&Bn[q >> 3][(q & 7) * 8] = bv[s];
      }
    }
    __syncthreads();
  }

  // ---- cross-kg reduction + Cs = fp16(2^24 * dinv_i * C) --------------------
  float* Rs = (float*)(smem + OFF_B0);          // 128 x 68 fp32 (34816 B)
  __half* Cs = (__half*)(smem + OFF_CS);        // 128 x 72 fp16 (18432 B)
  int g = lane >> 2, tig = lane & 3;

  if (kg == 1) {
#pragma unroll
    for (int mt = 0; mt < 2; mt++)
#pragma unroll
      for (int hr = 0; hr < 2; hr++) {
        int il = wm * 32 + mt * 16 + g + hr * 8;
#pragma unroll
        for (int nt = 0; nt < 4; nt++) {
          int col = wn * 32 + nt * 8 + tig * 2;
          *(float2*)&Rs[il * 68 + col] =
              make_float2(acc[mt][nt][hr * 2], acc[mt][nt][hr * 2 + 1]);
        }
      }
  }
  __syncthreads();
  if (kg == 0) {
#pragma unroll
    for (int mt = 0; mt < 2; mt++)
#pragma unroll
      for (int hr = 0; hr < 2; hr++) {
        int il = wm * 32 + mt * 16 + g + hr * 8;
        // compensate the 2^-24 subnormal encoding of A here (exact pow2)
        float dv = g_dinv[b * NN + i0 + il] * 16777216.0f;
#pragma unroll
        for (int nt = 0; nt < 4; nt++) {
          int col = wn * 32 + nt * 8 + tig * 2;
          float2 r = *(float2*)&Rs[il * 68 + col];
          __half2 hv =
              __floats2half2_rn((acc[mt][nt][hr * 2] + r.x) * dv,
                                (acc[mt][nt][hr * 2 + 1] + r.y) * dv);
          *(__half2*)&Cs[il * BS_STRIDE + col] = hv;
        }
      }
  }
  __syncthreads();

  // W-multiply: D = Cs @ (Whi + Wlo); warp grid m4 x n4, tile M32 x N16, K=64
  int warp_m = wid >> 2, warp_n = wid & 3;
  float acc2[2][2][4];
#pragma unroll
  for (int mt = 0; mt < 2; mt++)
#pragma unroll
    for (int nt = 0; nt < 2; nt++)
#pragma unroll
      for (int q = 0; q < 4; q++) acc2[mt][nt][q] = 0.0f;

#pragma unroll
  for (int ks = 0; ks < 4; ks++) {
    unsigned a2[2][4], bh[4], bl[4];
#pragma unroll
    for (int mt = 0; mt < 2; mt++)
      ldsm_x4(a2[mt], &Cs[(warp_m * 32 + mt * 16 + lr) * BS_STRIDE + ks * 16 + lc8]);
    ldsm_x4_t(bh, &Whi[(ks * 16 + lr) * BS_STRIDE + warp_n * 16 + lc8]);
    ldsm_x4_t(bl, &Wlo[(ks * 16 + lr) * BS_STRIDE + warp_n * 16 + lc8]);
#pragma unroll
    for (int mt = 0; mt < 2; mt++)
#pragma unroll
      for (int nt = 0; nt < 2; nt++) {
        mma16816(acc2[mt][nt], a2[mt], bh[nt * 2], bh[nt * 2 + 1]);
        mma16816(acc2[mt][nt], a2[mt], bl[nt * 2], bl[nt * 2 + 1]);
      }
  }

  // final epilogue
#pragma unroll
  for (int mt = 0; mt < 2; mt++) {
#pragma unroll
    for (int hr = 0; hr < 2; hr++) {
      int i = i0 + warp_m * 32 + mt * 16 + g + hr * 8;
      float dv = g_dinv[b * NN + i];
#pragma unroll
      for (int nt = 0; nt < 2; nt++) {
#pragma unroll
        for (int c2 = 0; c2 < 2; c2++) {
          int col = warp_n * 16 + nt * 8 + tig * 2 + c2;
          float v = acc2[mt][nt][hr * 2 + c2] + __ldg(&bias[col]);
          unsigned idx = ((unsigned)(b * NN + i)) * 64u + (unsigned)col;
          if (do_drop) {
            v = (v > 0.0f) ? v : expm1f(v);      // ELU
            v = drop_apply(v, idx, ka, kb);      // JAX threefry dropout
            tout[(size_t)i * DD + col] = __float2half(v * dv);
          } else {
            outp[idx] = v;
          }
        }
      }
    }
  }
}

// ---------------- launch ----------------------------------------------------
extern "C" void kernel_launch(void* const* d_in, const int* in_sizes, int n_in,
                              void* d_out, int out_size) {
  const float* x  = (const float*)d_in[0];
  const int*   adj= (const int*)d_in[1];
  const float* W1 = (const float*)d_in[2];
  const float* b1 = (const float*)d_in[3];
  const float* W2 = (const float*)d_in[4];
  const float* b2 = (const float*)d_in[5];
  const float* W3 = (const float*)d_in[6];
  const float* b3 = (const float*)d_in[7];
  float* out = (float*)d_out;

  (void)in_sizes; (void)n_in; (void)out_size;

  cudaFuncSetAttribute(agg_kernel, cudaFuncAttributeMaxDynamicSharedMemorySize,
                       AGG_DYN);

  prep_kernel<<<BB * NN, 128>>>(adj);
  scalex_kernel<<<(BB * NN * DD) / 8 / 256, 256>>>(x);

  dim3 agrid(NN / 128, BB);
  agg_kernel<<<agrid, 512, AGG_DYN>>>(W1, b1, nullptr, 0, cK1.a, cK1.b, 1);
  agg_kernel<<<agrid, 512, AGG_DYN>>>(W2, b2, nullptr, 1, cK2.a, cK2.b, 1);
  agg_kernel<<<agrid, 512, AGG_DYN>>>(W3, b3, out, 0, 0u, 0u, 0);
}

// round 16
// speedup vs baseline: 2.7595x; 1.1206x over previous
#include <cuda_runtime.h>
#include <cuda_fp16.h>

#define BB 4
#define NN 4096
#define DD 64

// ---------------- scratch (device globals; no allocation allowed) ----------
// bit-packed A, bytes permuted for fast fragment spread:
// byte t of each word = orig bits {2t,2t+1, 2t+8,2t+9, 2t+16,2t+17, 2t+24,2t+25}
__device__ __align__(16) unsigned g_Ap[(size_t)BB * NN * (NN / 32)];
__device__ float g_dinv[BB * NN];
// ping-pong fp16 feature buffers, row-major [b][j][d], pre-scaled by dinv_j
__device__ __align__(16) __half g_tb[2][(size_t)BB * NN * DD];

// ---------------- threefry2x32 (Random123 / JAX) ---------------------------
__host__ __device__ constexpr unsigned rotl32(unsigned x, int r) {
  return (x << r) | (x >> (32 - r));
}

__host__ __device__ constexpr void tf2x32(unsigned k0, unsigned k1,
                                          unsigned& x0, unsigned& x1) {
  unsigned k2 = k0 ^ k1 ^ 0x1BD11BDAu;
  x0 += k0; x1 += k1;
  x0+=x1; x1=rotl32(x1,13); x1^=x0;
  x0+=x1; x1=rotl32(x1,15); x1^=x0;
  x0+=x1; x1=rotl32(x1,26); x1^=x0;
  x0+=x1; x1=rotl32(x1, 6); x1^=x0;
  x0+=k1; x1+=k2+1u;
  x0+=x1; x1=rotl32(x1,17); x1^=x0;
  x0+=x1; x1=rotl32(x1,29); x1^=x0;
  x0+=x1; x1=rotl32(x1,16); x1^=x0;
  x0+=x1; x1=rotl32(x1,24); x1^=x0;
  x0+=k2; x1+=k0+2u;
  x0+=x1; x1=rotl32(x1,13); x1^=x0;
  x0+=x1; x1=rotl32(x1,15); x1^=x0;
  x0+=x1; x1=rotl32(x1,26); x1^=x0;
  x0+=x1; x1=rotl32(x1, 6); x1^=x0;
  x0+=k0; x1+=k1+3u;
  x0+=x1; x1=rotl32(x1,17); x1^=x0;
  x0+=x1; x1=rotl32(x1,29); x1^=x0;
  x0+=x1; x1=rotl32(x1,16); x1^=x0;
  x0+=x1; x1=rotl32(x1,24); x1^=x0;
  x0+=k1; x1+=k2+4u;
  x0+=x1; x1=rotl32(x1,13); x1^=x0;
  x0+=x1; x1=rotl32(x1,15); x1^=x0;
  x0+=x1; x1=rotl32(x1,26); x1^=x0;
  x0+=x1; x1=rotl32(x1, 6); x1^=x0;
  x0+=k2; x1+=k0+5u;
}

struct KeyPair { unsigned a, b; };
__host__ __device__ constexpr KeyPair derive_key(unsigned ctr) {
  unsigned x0 = 0u, x1 = ctr;
  tf2x32(0u, 42u, x0, x1);
  return KeyPair{x0, x1};
}
constexpr KeyPair cK1 = derive_key(0u);
constexpr KeyPair cK2 = derive_key(1u);

__device__ __forceinline__ float drop_apply(float v, unsigned idx,
                                            unsigned ka, unsigned kb) {
  unsigned y0 = 0u, y1 = idx;
  tf2x32(ka, kb, y0, y1);
  unsigned bits = y0 ^ y1;
  float u = __uint_as_float((bits >> 9) | 0x3f800000u) - 1.0f;
  return (u < 0.8f) ? v * 1.25f : 0.0f;
}

// ---------------- mma helpers (baseline sm_103-safe) ------------------------
__device__ __forceinline__ unsigned smem_u32(const void* p) {
  unsigned r;
  asm("{ .reg .u64 t; cvta.to.shared.u64 t, %1; cvt.u32.u64 %0, t; }"
      : "=r"(r) : "l"(p));
  return r;
}
__device__ __forceinline__ void ldsm_x4(unsigned* r, const void* p) {
  unsigned addr = smem_u32(p);
  asm volatile("ldmatrix.sync.aligned.m8n8.x4.shared.b16 {%0,%1,%2,%3}, [%4];"
               : "=r"(r[0]), "=r"(r[1]), "=r"(r[2]), "=r"(r[3]) : "r"(addr));
}
__device__ __forceinline__ void ldsm_x4_t(unsigned* r, const void* p) {
  unsigned addr = smem_u32(p);
  asm volatile("ldmatrix.sync.aligned.m8n8.x4.trans.shared.b16 {%0,%1,%2,%3}, [%4];"
               : "=r"(r[0]), "=r"(r[1]), "=r"(r[2]), "=r"(r[3]) : "r"(addr));
}
__device__ __forceinline__ void mma16816(float* c, const unsigned* a,
                                         unsigned b0, unsigned b1) {
  asm volatile(
      "mma.sync.aligned.m16n8k16.row.col.f32.f16.f16.f32 "
      "{%0,%1,%2,%3}, {%4,%5,%6,%7}, {%8,%9}, {%0,%1,%2,%3};"
      : "+f"(c[0]), "+f"(c[1]), "+f"(c[2]), "+f"(c[3])
      : "r"(a[0]), "r"(a[1]), "r"(a[2]), "r"(a[3]), "r"(b0), "r"(b1));
}

// ---------------- kernel 1: degrees + permuted bit-packed A + scaled x ------
__global__ __launch_bounds__(128) void prep_kernel(const int* __restrict__ adj,
                                                   const float* __restrict__ x) {
  int bi = blockIdx.x;
  int i  = bi & (NN - 1);
  const int4* row4 = (const int4*)(adj + (size_t)bi * NN);
  int tid = threadIdx.x;
  unsigned word = 0u;
#pragma unroll
  for (int s = 0; s < 8; s++) {
    int4 v = row4[tid * 8 + s];
    unsigned m = (unsigned)(v.x != 0) | ((unsigned)(v.y != 0) << 1) |
                 ((unsigned)(v.z != 0) << 2) | ((unsigned)(v.w != 0) << 3);
    word |= m << (s * 4);
  }
  if ((i >> 5) == tid) word |= 1u << (i & 31);   // self loop (orig bit order)

  // permute: byte t = bits {2t,2t+1, 2t+8,2t+9, 2t+16,2t+17, 2t+24,2t+25}
  unsigned wp = 0u;
#pragma unroll
  for (int t = 0; t < 4; t++) {
    unsigned by = ((word >> (2 * t)) & 3u) |
                  (((word >> (2 * t + 8)) & 3u) << 2) |
                  (((word >> (2 * t + 16)) & 3u) << 4) |
                  (((word >> (2 * t + 24)) & 3u) << 6);
    wp |= by << (8 * t);
  }
  g_Ap[(size_t)bi * 128 + tid] = wp;

  int cnt = __popc(word);
  __shared__ int red[4];
  int wsum = __reduce_add_sync(0xffffffffu, cnt);
  if ((tid & 31) == 0) red[tid >> 5] = wsum;
  __syncthreads();
  float dv = rsqrtf((float)(red[0] + red[1] + red[2] + red[3]));
  if (tid == 0) g_dinv[bi] = dv;
  // fused scalex: t0[j][d] = fp16(dinv_j * x[j][d])
  if (tid < 64)
    g_tb[0][(size_t)bi * 64 + tid] =
        __float2half(x[(size_t)bi * 64 + tid] * dv);
}

// ---------------- kernel 2: fused  out = dinv_i*(A@t)@W + b [; elu; drop] ---
// M-tile = 128, K-chunk = 128, 512 threads, warp grid (m4, k2, n2).
// A stays packed; fragments built in regs via PRMT byte extract + x0x8001
// spread; '1' encoded as fp16 subnormal 0x0001 (2^-24), compensated by
// folding 2^24 into the dinv_i epilogue scale.
#define BS_STRIDE 72
#define OFF_B0 0
#define OFF_B1 18432
#define OFF_AP0 36864
#define OFF_AP1 38912
#define OFF_WHI 40960
#define OFF_WLO 50176
#define OFF_CS  59392
#define AGG_DYN 77824

__global__ __launch_bounds__(512, 1) void agg_kernel(
    const float* __restrict__ Wm, const float* __restrict__ bias,
    float* __restrict__ outp, int tin_sel,
    unsigned ka, unsigned kb, int do_drop) {
  extern __shared__ __align__(16) char smem[];
  __half* Whi = (__half*)(smem + OFF_WHI);
  __half* Wlo = (__half*)(smem + OFF_WLO);

  int tid = threadIdx.x, wid = tid >> 5, lane = tid & 31;
  // mainloop warp grid: m4 x k2 x n2
  int wm = wid >> 2, kg = (wid >> 1) & 1, wn = wid & 1;
  int b = blockIdx.y, i0 = blockIdx.x * 128;

  // W hi/lo split
#pragma unroll
  for (int s = 0; s < 8; s++) {
    int idx = tid + 512 * s;
    int r = idx >> 6, c = idx & 63;
    float w = Wm[idx];
    __half hh = __float2half(w);
    Whi[r * BS_STRIDE + c] = hh;
    Wlo[r * BS_STRIDE + c] = __float2half(w - __half2float(hh));
  }

  const unsigned* Ap = g_Ap + ((size_t)b * NN + i0) * 128;
  const __half* tin = g_tb[tin_sel] + (size_t)b * NN * DD;
  __half* tout = g_tb[tin_sel ^ 1] + (size_t)b * NN * DD;

  // packed-A fill mapping: 4 threads per row (word = tid&3), row = tid>>2
  int prow = tid >> 2;
  int pwo  = tid & 3;

  float acc[2][4][4];
#pragma unroll
  for (int mt = 0; mt < 2; mt++)
#pragma unroll
    for (int nt = 0; nt < 4; nt++)
#pragma unroll
      for (int q = 0; q < 4; q++) acc[mt][nt][q] = 0.0f;

  int lr = lane & 15, lc8 = (lane >> 4) << 3;
  unsigned psel = 0x4440u | (unsigned)(lane & 3);  // PRMT byte-extract selector
  // rows whose bits this thread needs (per m-tile)
  int fr0 = wm * 32 + (lane >> 2);     // mt=0 rows: fr0, fr0+8 ; mt=1: +16

  // staged registers
  unsigned apw;
  uint4 bv[2];

  // preload + store chunk 0 into buffer 0
  apw = Ap[(size_t)prow * 128 + pwo];
#pragma unroll
  for (int s = 0; s < 2; s++) {
    int q = tid + 512 * s;
    bv[s] = *(const uint4*)&tin[(size_t)(q >> 3) * DD + (q & 7) * 8];
  }
  {
    unsigned* Apk = (unsigned*)(smem + OFF_AP0);
    __half (*Bs)[BS_STRIDE] = (__half(*)[BS_STRIDE])(smem + OFF_B0);
    Apk[tid] = apw;                         // layout [row][word], row*16B
#pragma unroll
    for (int s = 0; s < 2; s++) {
      int q = tid + 512 * s;
      *(uint4*)&Bs[q >> 3][(q & 7) * 8] = bv[s];
    }
  }
  __syncthreads();

  for (int c = 0; c < 32; c++) {
    int cur = c & 1;
    char* apbuf = smem + (cur ? OFF_AP1 : OFF_AP0);
    __half (*Bs)[BS_STRIDE] =
        (__half(*)[BS_STRIDE])(smem + (cur ? OFF_B1 : OFF_B0));
    // issue global loads for chunk c+1 (latency hidden behind MMAs)
    if (c < 31) {
      int knw = (c + 1) * 4;
      apw = Ap[(size_t)prow * 128 + knw + pwo];
#pragma unroll
      for (int s = 0; s < 2; s++) {
        int q = tid + 512 * s;
        bv[s] = *(const uint4*)&tin[(size_t)((c + 1) * 128 + (q >> 3)) * DD +
                                    (q & 7) * 8];
      }
    }
    // pull this warp's packed K64 slice, extract byte, multiply-spread:
    // spread bit i of byte -> positions i and i+15; then each a-register is
    // a single (>>sh)&0x00010001.
    unsigned spr[2][2][2];   // [mt][rowA/rowB][word]
#pragma unroll
    for (int mt = 0; mt < 2; mt++) {
      int ra = fr0 + mt * 16;
      uint2 wa2 = *(uint2*)(apbuf + ra * 16 + kg * 8);
      uint2 wb2 = *(uint2*)(apbuf + (ra + 8) * 16 + kg * 8);
      spr[mt][0][0] = __byte_perm(wa2.x, 0u, psel) * 0x8001u;
      spr[mt][0][1] = __byte_perm(wa2.y, 0u, psel) * 0x8001u;
      spr[mt][1][0] = __byte_perm(wb2.x, 0u, psel) * 0x8001u;
      spr[mt][1][1] = __byte_perm(wb2.y, 0u, psel) * 0x8001u;
    }
    // MMA on current buffer: warp's K-slice = [kg*64, kg*64+64)
#pragma unroll
    for (int ks = 0; ks < 4; ks++) {
      int kc = kg * 64 + ks * 16;
      unsigned bf[2][4];
#pragma unroll
      for (int nh = 0; nh < 2; nh++)
        ldsm_x4_t(bf[nh], &Bs[kc + lr][wn * 32 + nh * 16 + lc8]);
      unsigned a[2][4];
      int sh = (ks & 1) * 4;
#pragma unroll
      for (int mt = 0; mt < 2; mt++) {
        unsigned sa = spr[mt][0][ks >> 1];
        unsigned sb = spr[mt][1][ks >> 1];
        a[mt][0] = (sa >> sh) & 0x00010001u;
        a[mt][1] = (sb >> sh) & 0x00010001u;
        a[mt][2] = (sa >> (sh + 2)) & 0x00010001u;
        a[mt][3] = (sb >> (sh + 2)) & 0x00010001u;
      }
#pragma unroll
      for (int mt = 0; mt < 2; mt++)
#pragma unroll
        for (int nt = 0; nt < 4; nt++)
          mma16816(acc[mt][nt], a[mt],
                   bf[nt >> 1][(nt & 1) * 2], bf[nt >> 1][(nt & 1) * 2 + 1]);
    }
    // store staged chunk c+1
    if (c < 31) {
      unsigned* Apn = (unsigned*)(smem + (cur ? OFF_AP0 : OFF_AP1));
      __half (*Bn)[BS_STRIDE] =
          (__half(*)[BS_STRIDE])(smem + (cur ? OFF_B0 : OFF_B1));
      Apn[tid] = apw;
#pragma unroll
      for (int s = 0; s < 2; s++) {
        int q = tid + 512 * s;
        *(uint4*)&Bn[q >> 3][(q & 7) * 8] = bv[s];
      }
    }
    __syncthreads();
  }

  // ---- cross-kg reduction + Cs = fp16(2^24 * dinv_i * C) --------------------
  float* Rs = (float*)(smem + OFF_B0);          // 128 x 68 fp32 (34816 B)
  __half* Cs = (__half*)(smem + OFF_CS);        // 128 x 72 fp16 (18432 B)
  int g = lane >> 2, tig = lane & 3;

  if (kg == 1) {
#pragma unroll
    for (int mt = 0; mt < 2; mt++)
#pragma unroll
      for (int hr = 0; hr < 2; hr++) {
        int il = wm * 32 + mt * 16 + g + hr * 8;
#pragma unroll
        for (int nt = 0; nt < 4; nt++) {
          int col = wn * 32 + nt * 8 + tig * 2;
          *(float2*)&Rs[il * 68 + col] =
              make_float2(acc[mt][nt][hr * 2], acc[mt][nt][hr * 2 + 1]);
        }
      }
  }
  __syncthreads();
  if (kg == 0) {
#pragma unroll
    for (int mt = 0; mt < 2; mt++)
#pragma unroll
      for (int hr = 0; hr < 2; hr++) {
        int il = wm * 32 + mt * 16 + g + hr * 8;
        // compensate the 2^-24 subnormal encoding of A here (exact pow2)
        float dv = g_dinv[b * NN + i0 + il] * 16777216.0f;
#pragma unroll
        for (int nt = 0; nt < 4; nt++) {
          int col = wn * 32 + nt * 8 + tig * 2;
          float2 r = *(float2*)&Rs[il * 68 + col];
          __half2 hv =
              __floats2half2_rn((acc[mt][nt][hr * 2] + r.x) * dv,
                                (acc[mt][nt][hr * 2 + 1] + r.y) * dv);
          *(__half2*)&Cs[il * BS_STRIDE + col] = hv;
        }
      }
  }
  __syncthreads();

  // W-multiply: D = Cs @ (Whi + Wlo); warp grid m4 x n4, tile M32 x N16, K=64
  int warp_m = wid >> 2, warp_n = wid & 3;
  float acc2[2][2][4];
#pragma unroll
  for (int mt = 0; mt < 2; mt++)
#pragma unroll
    for (int nt = 0; nt < 2; nt++)
#pragma unroll
      for (int q = 0; q < 4; q++) acc2[mt][nt][q] = 0.0f;

#pragma unroll
  for (int ks = 0; ks < 4; ks++) {
    unsigned a2[2][4], bh[4], bl[4];
#pragma unroll
    for (int mt = 0; mt < 2; mt++)
      ldsm_x4(a2[mt], &Cs[(warp_m * 32 + mt * 16 + lr) * BS_STRIDE + ks * 16 + lc8]);
    ldsm_x4_t(bh, &Whi[(ks * 16 + lr) * BS_STRIDE + warp_n * 16 + lc8]);
    ldsm_x4_t(bl, &Wlo[(ks * 16 + lr) * BS_STRIDE + warp_n * 16 + lc8]);
#pragma unroll
    for (int mt = 0; mt < 2; mt++)
#pragma unroll
      for (int nt = 0; nt < 2; nt++) {
        mma16816(acc2[mt][nt], a2[mt], bh[nt * 2], bh[nt * 2 + 1]);
        mma16816(acc2[mt][nt], a2[mt], bl[nt * 2], bl[nt * 2 + 1]);
      }
  }

  // final epilogue
#pragma unroll
  for (int mt = 0; mt < 2; mt++) {
#pragma unroll
    for (int hr = 0; hr < 2; hr++) {
      int i = i0 + warp_m * 32 + mt * 16 + g + hr * 8;
      float dv = g_dinv[b * NN + i];
#pragma unroll
      for (int nt = 0; nt < 2; nt++) {
#pragma unroll
        for (int c2 = 0; c2 < 2; c2++) {
          int col = warp_n * 16 + nt * 8 + tig * 2 + c2;
          float v = acc2[mt][nt][hr * 2 + c2] + __ldg(&bias[col]);
          unsigned idx = ((unsigned)(b * NN + i)) * 64u + (unsigned)col;
          if (do_drop) {
            v = (v > 0.0f) ? v : expm1f(v);      // ELU
            v = drop_apply(v, idx, ka, kb);      // JAX threefry dropout
            tout[(size_t)i * DD + col] = __float2half(v * dv);
          } else {
            outp[idx] = v;
          }
        }
      }
    }
  }
}

// ---------------- launch ----------------------------------------------------
extern "C" void kernel_launch(void* const* d_in, const int* in_sizes, int n_in,
                              void* d_out, int out_size) {
  const float* x  = (const float*)d_in[0];
  const int*   adj= (const int*)d_in[1];
  const float* W1 = (const float*)d_in[2];
  const float* b1 = (const float*)d_in[3];
  const float* W2 = (const float*)d_in[4];
  const float* b2 = (const float*)d_in[5];
  const float* W3 = (const float*)d_in[6];
  const float* b3 = (const float*)d_in[7];
  float* out = (float*)d_out;

  (void)in_sizes; (void)n_in; (void)out_size;

  cudaFuncSetAttribute(agg_kernel, cudaFuncAttributeMaxDynamicSharedMemorySize,
                       AGG_DYN);

  prep_kernel<<<BB * NN, 128>>>(adj, x);

  dim3 agrid(NN / 128, BB);
  agg_kernel<<<agrid, 512, AGG_DYN>>>(W1, b1, nullptr, 0, cK1.a, cK1.b, 1);
  agg_kernel<<<agrid, 512, AGG_DYN>>>(W2, b2, nullptr, 1, cK2.a, cK2.b, 1);
  agg_kernel<<<agrid, 512, AGG_DYN>>>(W3, b3, out, 0, 0u, 0u, 0);
}